// round 1
// baseline (speedup 1.0000x reference)
#include <cuda_runtime.h>
#include <math.h>

#define BB 4
#define SS 4096
#define DD 1024
#define HALF (DD/2)
#define TD (3*DD)

// ---------------- scratch (device globals; no allocation allowed) ----------------
__device__ __align__(16) float g_h[(long long)BB*SS*DD];        // rmsnorm output  (64MB)
__device__ __align__(16) float g_qkv[(long long)BB*SS*TD];      // qkv (rope applied in place) (192MB)
__device__ __align__(16) float g_scores[(long long)BB*SS*SS];   // attention scores / weights  (256MB)
__device__ __align__(16) float g_attnv[(long long)BB*SS*DD];    // attn @ V (64MB)
__device__ signed char g_cos[SS*HALF];
__device__ signed char g_sin[SS*HALF];

// ---------------- ternary rope tables ----------------
// Reproduce JAX fp32 chain: e = j/512 (exact); p = powf(10000, e) (assume correctly
// rounded -> reproduce via double pow + round-to-float); inv = 1.0f/p (fp32 div);
// ang = (float)s * inv (fp32 mul). cos/sin evaluated in double, then round-to-nearest-even.
__global__ void build_tables_kernel() {
    int idx = blockIdx.x * blockDim.x + threadIdx.x;
    if (idx >= SS * HALF) return;
    int s = idx / HALF;
    int j = idx - s * HALF;
    float e = (float)j / (float)HALF;                 // exact (denominator is 2^9)
    float p = (float)pow(10000.0, (double)e);         // == correctly-rounded powf
    float invf = 1.0f / p;                            // fp32 division (correctly rounded)
    float ang = (float)s * invf;                      // fp32 multiply
    double c, sn;
    sincos((double)ang, &sn, &c);
    g_cos[idx] = (signed char)lrint(c);               // round half-to-even, matches jnp.round
    g_sin[idx] = (signed char)lrint(sn);
}

// ---------------- block reductions ----------------
__device__ __forceinline__ float block_reduce_sum(float v, float* red) {
    int lane = threadIdx.x & 31, w = threadIdx.x >> 5;
    #pragma unroll
    for (int o = 16; o; o >>= 1) v += __shfl_xor_sync(0xffffffffu, v, o);
    if (lane == 0) red[w] = v;
    __syncthreads();
    if (w == 0) {
        v = (lane < (int)(blockDim.x >> 5)) ? red[lane] : 0.0f;
        #pragma unroll
        for (int o = 16; o; o >>= 1) v += __shfl_xor_sync(0xffffffffu, v, o);
        if (lane == 0) red[0] = v;
    }
    __syncthreads();
    float out = red[0];
    __syncthreads();
    return out;
}

__device__ __forceinline__ float block_reduce_max(float v, float* red) {
    int lane = threadIdx.x & 31, w = threadIdx.x >> 5;
    #pragma unroll
    for (int o = 16; o; o >>= 1) v = fmaxf(v, __shfl_xor_sync(0xffffffffu, v, o));
    if (lane == 0) red[w] = v;
    __syncthreads();
    if (w == 0) {
        v = (lane < (int)(blockDim.x >> 5)) ? red[lane] : -INFINITY;
        #pragma unroll
        for (int o = 16; o; o >>= 1) v = fmaxf(v, __shfl_xor_sync(0xffffffffu, v, o));
        if (lane == 0) red[0] = v;
    }
    __syncthreads();
    float out = red[0];
    __syncthreads();
    return out;
}

// ---------------- rmsnorm ----------------
// one block (256 threads) per row of 1024 floats; float4 vectorized
__global__ __launch_bounds__(256) void rmsnorm_kernel(const float* __restrict__ x,
                                                      const float* __restrict__ g,
                                                      float* __restrict__ h) {
    __shared__ float red[32];
    long long base = (long long)blockIdx.x * DD;
    float4 v = *(const float4*)(x + base + (long long)threadIdx.x * 4);
    float ss = v.x*v.x + v.y*v.y + v.z*v.z + v.w*v.w;
    float total = block_reduce_sum(ss, red);
    float r = rsqrtf(total * (1.0f / DD) + 1e-6f);
    float4 gv = *(const float4*)(g + (long long)threadIdx.x * 4);
    float4 o;
    o.x = v.x * r * gv.x; o.y = v.y * r * gv.y; o.z = v.z * r * gv.z; o.w = v.w * r * gv.w;
    *(float4*)(h + base + (long long)threadIdx.x * 4) = o;
}

// ---------------- rope (in place on q and k parts of qkv) ----------------
__global__ __launch_bounds__(512) void rope_kernel(float* __restrict__ qkv) {
    int bs = blockIdx.x;             // 0 .. B*S-1
    int s = bs & (SS - 1);
    int j = threadIdx.x;             // 0..511
    float c  = (float)g_cos[s * HALF + j];
    float sn = (float)g_sin[s * HALF + j];
    float* q = qkv + (long long)bs * TD;
    float* k = q + DD;
    float a = q[j], b = q[j + HALF];
    q[j]        = a * c - b * sn;
    q[j + HALF] = b * c + a * sn;
    a = k[j]; b = k[j + HALF];
    k[j]        = a * c - b * sn;
    k[j + HALF] = b * c + a * sn;
}

// ---------------- base-3 softmax (stable) over rows of 4096 ----------------
__global__ __launch_bounds__(256) void softmax3_kernel(float* __restrict__ sc) {
    __shared__ __align__(16) float buf[SS];
    __shared__ float red[32];
    long long base = (long long)blockIdx.x * SS;
    float4* gp = (float4*)(sc + base);
    float4* sb = (float4*)buf;
    float m = -INFINITY;
    #pragma unroll
    for (int i = 0; i < 4; i++) {
        float4 v = gp[threadIdx.x + i * 256];
        sb[threadIdx.x + i * 256] = v;
        m = fmaxf(m, fmaxf(fmaxf(v.x, v.y), fmaxf(v.z, v.w)));
    }
    m = block_reduce_max(m, red);
    const float L23 = 1.5849625007211562f;   // log2(3)
    float sum = 0.0f;
    #pragma unroll
    for (int i = 0; i < 4; i++) {
        float4 v = sb[threadIdx.x + i * 256];
        v.x = exp2f((v.x - m) * L23);
        v.y = exp2f((v.y - m) * L23);
        v.z = exp2f((v.z - m) * L23);
        v.w = exp2f((v.w - m) * L23);
        sb[threadIdx.x + i * 256] = v;
        sum += v.x + v.y + v.z + v.w;
    }
    sum = block_reduce_sum(sum, red);
    float inv = 1.0f / sum;
    #pragma unroll
    for (int i = 0; i < 4; i++) {
        float4 v = sb[threadIdx.x + i * 256];
        v.x *= inv; v.y *= inv; v.z *= inv; v.w *= inv;
        gp[threadIdx.x + i * 256] = v;
    }
}

// ---------------- generic fp32 GEMM: C = alpha * A @ op(B) [+ bias] [+ resid] ----------------
// TRANSB==0: B is [K,N] (ldb), TRANSB==1: B is [N,K] (ldb), i.e. C = A @ B^T.
// 128x128 tile, BK=8, 256 threads, 8x8 per thread. All dims must be multiples of 128/8 (they are).
template <int TRANSB>
__global__ __launch_bounds__(256) void sgemm_kernel(
    int M, int N, int K,
    const float* __restrict__ A, int lda, long long strideA,
    const float* __restrict__ Bm, int ldb, long long strideB,
    float* __restrict__ C, int ldc, long long strideC,
    float alpha,
    const float* __restrict__ bias,
    const float* __restrict__ resid)
{
    __shared__ __align__(16) float As[8][128];
    __shared__ __align__(16) float Bs[8][128];

    const int tid = threadIdx.x;
    const int bx = blockIdx.x, by = blockIdx.y, bz = blockIdx.z;
    A  += (long long)bz * strideA;
    Bm += (long long)bz * strideB;
    C  += (long long)bz * strideC;

    const int arow = tid >> 1;
    const int acol = (tid & 1) * 4;
    const float* Aptr = A + (long long)(by * 128 + arow) * lda + acol;

    const float* Bptr;
    int brow, bcol;
    if (TRANSB) {
        brow = tid >> 1; bcol = (tid & 1) * 4;
        Bptr = Bm + (long long)(bx * 128 + brow) * ldb + bcol;
    } else {
        brow = tid >> 5; bcol = (tid & 31) * 4;
        Bptr = Bm + (long long)brow * ldb + bx * 128 + bcol;
    }

    float acc[8][8];
    #pragma unroll
    for (int i = 0; i < 8; i++)
        #pragma unroll
        for (int j = 0; j < 8; j++) acc[i][j] = 0.0f;

    const int ty = tid >> 4, tx = tid & 15;
    const int row0 = ty * 8, col0 = tx * 8;

    for (int kt = 0; kt < K; kt += 8) {
        float4 av = *(const float4*)Aptr;
        Aptr += 8;
        As[acol + 0][arow] = av.x; As[acol + 1][arow] = av.y;
        As[acol + 2][arow] = av.z; As[acol + 3][arow] = av.w;

        float4 bv = *(const float4*)Bptr;
        if (TRANSB) {
            Bptr += 8;
            Bs[bcol + 0][brow] = bv.x; Bs[bcol + 1][brow] = bv.y;
            Bs[bcol + 2][brow] = bv.z; Bs[bcol + 3][brow] = bv.w;
        } else {
            Bptr += (long long)8 * ldb;
            *(float4*)&Bs[brow][bcol] = bv;
        }
        __syncthreads();

        #pragma unroll
        for (int k = 0; k < 8; k++) {
            float4 a0 = *(const float4*)&As[k][row0];
            float4 a1 = *(const float4*)&As[k][row0 + 4];
            float4 b0 = *(const float4*)&Bs[k][col0];
            float4 b1 = *(const float4*)&Bs[k][col0 + 4];
            float a[8] = {a0.x, a0.y, a0.z, a0.w, a1.x, a1.y, a1.z, a1.w};
            float b[8] = {b0.x, b0.y, b0.z, b0.w, b1.x, b1.y, b1.z, b1.w};
            #pragma unroll
            for (int i = 0; i < 8; i++)
                #pragma unroll
                for (int j = 0; j < 8; j++)
                    acc[i][j] = fmaf(a[i], b[j], acc[i][j]);
        }
        __syncthreads();
    }

    // epilogue
    float bvals[8];
    #pragma unroll
    for (int j = 0; j < 8; j++)
        bvals[j] = bias ? __ldg(&bias[bx * 128 + col0 + j]) : 0.0f;

    #pragma unroll
    for (int i = 0; i < 8; i++) {
        long long grow = (long long)(by * 128 + row0 + i);
        float* crow = C + grow * ldc + bx * 128 + col0;
        const float* rrow = resid ? (resid + grow * ldc + bx * 128 + col0) : nullptr;
        float out[8];
        #pragma unroll
        for (int j = 0; j < 8; j++) {
            float v = acc[i][j] * alpha + bvals[j];
            if (resid) v += rrow[j];
            out[j] = v;
        }
        *(float4*)&crow[0] = *(float4*)&out[0];
        *(float4*)&crow[4] = *(float4*)&out[4];
    }
}

// ---------------- launch ----------------
extern "C" void kernel_launch(void* const* d_in, const int* in_sizes, int n_in,
                              void* d_out, int out_size) {
    const float* x      = (const float*)d_in[0];
    const float* g_norm = (const float*)d_in[1];
    const float* w_qkv  = (const float*)d_in[2];
    const float* b_qkv  = (const float*)d_in[3];
    const float* w_proj = (const float*)d_in[4];
    const float* b_proj = (const float*)d_in[5];
    float* out = (float*)d_out;

    void *ph, *pqkv, *psc, *pav;
    cudaGetSymbolAddress(&ph, g_h);
    cudaGetSymbolAddress(&pqkv, g_qkv);
    cudaGetSymbolAddress(&psc, g_scores);
    cudaGetSymbolAddress(&pav, g_attnv);
    float* h      = (float*)ph;
    float* qkv    = (float*)pqkv;
    float* scores = (float*)psc;
    float* attnv  = (float*)pav;

    const float scale = 1.0f / 32.0f;   // 1/sqrt(1024)

    // 1) ternary rope tables
    build_tables_kernel<<<(SS * HALF + 255) / 256, 256>>>();

    // 2) rmsnorm
    rmsnorm_kernel<<<BB * SS, 256>>>(x, g_norm, h);

    // 3) qkv = h @ w_qkv + b_qkv   [16384,1024]x[1024,3072]
    sgemm_kernel<0><<<dim3(TD / 128, (BB * SS) / 128, 1), 256>>>(
        BB * SS, TD, DD,
        h, DD, 0LL,
        w_qkv, TD, 0LL,
        qkv, TD, 0LL,
        1.0f, b_qkv, nullptr);

    // 4) ternary rope on q,k in place
    rope_kernel<<<BB * SS, 512>>>(qkv);

    // 5) scores[b] = scale * Q[b] @ K[b]^T   per batch [4096,1024]x[4096,1024]^T
    sgemm_kernel<1><<<dim3(SS / 128, SS / 128, BB), 256>>>(
        SS, SS, DD,
        qkv, TD, (long long)SS * TD,
        qkv + DD, TD, (long long)SS * TD,
        scores, SS, (long long)SS * SS,
        scale, nullptr, nullptr);

    // 6) base-3 softmax rows
    softmax3_kernel<<<BB * SS, 256>>>(scores);

    // 7) attnv[b] = scores[b] @ V[b]   [4096,4096]x[4096,1024]
    sgemm_kernel<0><<<dim3(DD / 128, SS / 128, BB), 256>>>(
        SS, DD, SS,
        scores, SS, (long long)SS * SS,
        qkv + 2 * DD, TD, (long long)SS * TD,
        attnv, DD, (long long)SS * DD,
        1.0f, nullptr, nullptr);

    // 8) out = attnv @ w_proj + b_proj + x
    sgemm_kernel<0><<<dim3(DD / 128, (BB * SS) / 128, 1), 256>>>(
        BB * SS, DD, DD,
        attnv, DD, 0LL,
        w_proj, DD, 0LL,
        out, DD, 0LL,
        1.0f, b_proj, x);
}

// round 2
// speedup vs baseline: 5.0545x; 5.0545x over previous
#include <cuda_runtime.h>
#include <cuda_bf16.h>
#include <math.h>

#define BB 4
#define SS 4096
#define DD 1024
#define HALF (DD/2)
#define TD (3*DD)

// ---------------- scratch (device globals; no allocation allowed) ----------------
__device__ __align__(16) float          g_qkv[(long long)BB*SS*TD];     // 192MB fp32
__device__ __align__(16) float          g_scores[(long long)BB*SS*SS];  // 256MB fp32
__device__ __align__(16) __nv_bfloat16  g_attnbf[(long long)BB*SS*SS];  // 128MB
__device__ __align__(16) __nv_bfloat16  g_hbf[(long long)BB*SS*DD];     // 32MB
__device__ __align__(16) __nv_bfloat16  g_qbf[(long long)BB*SS*DD];     // 32MB
__device__ __align__(16) __nv_bfloat16  g_kbf[(long long)BB*SS*DD];     // 32MB
__device__ __align__(16) __nv_bfloat16  g_vT[(long long)BB*DD*SS];      // 32MB [b][d][t]
__device__ __align__(16) __nv_bfloat16  g_avbf[(long long)BB*SS*DD];    // 32MB
__device__ __align__(16) __nv_bfloat16  g_wqkvT[(long long)TD*DD];      // 6MB  [n][k]
__device__ __align__(16) __nv_bfloat16  g_wprojT[(long long)DD*DD];     // 2MB  [n][k]
__device__ signed char g_cos[SS*HALF];
__device__ signed char g_sin[SS*HALF];

// ---------------- ternary rope tables (exact fp32 chain, double trig) ----------------
__global__ void build_tables_kernel() {
    int idx = blockIdx.x * blockDim.x + threadIdx.x;
    if (idx >= SS * HALF) return;
    int s = idx / HALF;
    int j = idx - s * HALF;
    float e = (float)j / (float)HALF;
    float p = (float)pow(10000.0, (double)e);
    float invf = 1.0f / p;
    float ang = (float)s * invf;
    double c, sn;
    sincos((double)ang, &sn, &c);
    g_cos[idx] = (signed char)lrint(c);
    g_sin[idx] = (signed char)lrint(sn);
}

// ---------------- reductions ----------------
__device__ __forceinline__ float block_reduce_sum(float v, float* red) {
    int lane = threadIdx.x & 31, w = threadIdx.x >> 5;
    #pragma unroll
    for (int o = 16; o; o >>= 1) v += __shfl_xor_sync(0xffffffffu, v, o);
    if (lane == 0) red[w] = v;
    __syncthreads();
    if (w == 0) {
        v = (lane < (int)(blockDim.x >> 5)) ? red[lane] : 0.0f;
        #pragma unroll
        for (int o = 16; o; o >>= 1) v += __shfl_xor_sync(0xffffffffu, v, o);
        if (lane == 0) red[0] = v;
    }
    __syncthreads();
    float out = red[0];
    __syncthreads();
    return out;
}
__device__ __forceinline__ float block_reduce_max(float v, float* red) {
    int lane = threadIdx.x & 31, w = threadIdx.x >> 5;
    #pragma unroll
    for (int o = 16; o; o >>= 1) v = fmaxf(v, __shfl_xor_sync(0xffffffffu, v, o));
    if (lane == 0) red[w] = v;
    __syncthreads();
    if (w == 0) {
        v = (lane < (int)(blockDim.x >> 5)) ? red[lane] : -INFINITY;
        #pragma unroll
        for (int o = 16; o; o >>= 1) v = fmaxf(v, __shfl_xor_sync(0xffffffffu, v, o));
        if (lane == 0) red[0] = v;
    }
    __syncthreads();
    float out = red[0];
    __syncthreads();
    return out;
}

// ---------------- rmsnorm -> bf16 ----------------
__global__ __launch_bounds__(256) void rmsnorm_kernel(const float* __restrict__ x,
                                                      const float* __restrict__ g,
                                                      __nv_bfloat16* __restrict__ h) {
    __shared__ float red[32];
    long long base = (long long)blockIdx.x * DD;
    float4 v = *(const float4*)(x + base + (long long)threadIdx.x * 4);
    float ss = v.x*v.x + v.y*v.y + v.z*v.z + v.w*v.w;
    float total = block_reduce_sum(ss, red);
    float r = rsqrtf(total * (1.0f / DD) + 1e-6f);
    float4 gv = *(const float4*)(g + (long long)threadIdx.x * 4);
    __nv_bfloat162 o0 = {__float2bfloat16(v.x*r*gv.x), __float2bfloat16(v.y*r*gv.y)};
    __nv_bfloat162 o1 = {__float2bfloat16(v.z*r*gv.z), __float2bfloat16(v.w*r*gv.w)};
    __nv_bfloat162* hp = (__nv_bfloat162*)(h + base + (long long)threadIdx.x * 4);
    hp[0] = o0; hp[1] = o1;
}

// ---------------- transpose + convert f32 -> bf16: out[c][r] = in[r][c] ----------------
__global__ __launch_bounds__(256) void transpose_cvt_kernel(
    const float* __restrict__ in, long long sIn, int ldin,
    __nv_bfloat16* __restrict__ out, long long sOut, int ldout,
    int R, int C)
{
    __shared__ float tile[32][33];
    int z = blockIdx.z;
    int r0 = blockIdx.y * 32, c0 = blockIdx.x * 32;
    int tx = threadIdx.x & 31, ty = threadIdx.x >> 5;  // 32 x 8
    const float* ip = in + (long long)z * sIn;
    #pragma unroll
    for (int i = 0; i < 4; i++) {
        int r = r0 + ty + i * 8;
        tile[ty + i * 8][tx] = ip[(long long)r * ldin + c0 + tx];
    }
    __syncthreads();
    __nv_bfloat16* op = out + (long long)z * sOut;
    #pragma unroll
    for (int i = 0; i < 4; i++) {
        int c = c0 + ty + i * 8;
        op[(long long)c * ldout + r0 + tx] = __float2bfloat16(tile[tx][ty + i * 8]);
    }
}

// ---------------- rope: qkv fp32 -> qbf, kbf bf16 ----------------
__global__ __launch_bounds__(512) void rope_kernel(const float* __restrict__ qkv,
                                                   __nv_bfloat16* __restrict__ qo,
                                                   __nv_bfloat16* __restrict__ ko) {
    int bs = blockIdx.x;
    int s = bs & (SS - 1);
    int j = threadIdx.x;
    float c  = (float)g_cos[s * HALF + j];
    float sn = (float)g_sin[s * HALF + j];
    const float* q = qkv + (long long)bs * TD;
    const float* k = q + DD;
    long long ob = (long long)bs * DD;
    float a = q[j], b = q[j + HALF];
    qo[ob + j]        = __float2bfloat16(a * c - b * sn);
    qo[ob + j + HALF] = __float2bfloat16(b * c + a * sn);
    a = k[j]; b = k[j + HALF];
    ko[ob + j]        = __float2bfloat16(a * c - b * sn);
    ko[ob + j + HALF] = __float2bfloat16(b * c + a * sn);
}

// ---------------- base-3 softmax: f32 scores -> bf16 attn ----------------
__global__ __launch_bounds__(256) void softmax3_kernel(const float* __restrict__ sc,
                                                       __nv_bfloat16* __restrict__ attn) {
    __shared__ __align__(16) float buf[SS];
    __shared__ float red[32];
    long long base = (long long)blockIdx.x * SS;
    const float4* gp = (const float4*)(sc + base);
    float4* sb = (float4*)buf;
    float m = -INFINITY;
    #pragma unroll
    for (int i = 0; i < 4; i++) {
        float4 v = gp[threadIdx.x + i * 256];
        sb[threadIdx.x + i * 256] = v;
        m = fmaxf(m, fmaxf(fmaxf(v.x, v.y), fmaxf(v.z, v.w)));
    }
    m = block_reduce_max(m, red);
    const float L23 = 1.5849625007211562f;
    float sum = 0.0f;
    #pragma unroll
    for (int i = 0; i < 4; i++) {
        float4 v = sb[threadIdx.x + i * 256];
        v.x = exp2f((v.x - m) * L23); v.y = exp2f((v.y - m) * L23);
        v.z = exp2f((v.z - m) * L23); v.w = exp2f((v.w - m) * L23);
        sb[threadIdx.x + i * 256] = v;
        sum += v.x + v.y + v.z + v.w;
    }
    sum = block_reduce_sum(sum, red);
    float inv = 1.0f / sum;
    __nv_bfloat162* op = (__nv_bfloat162*)(attn + base);
    #pragma unroll
    for (int i = 0; i < 4; i++) {
        float4 v = sb[threadIdx.x + i * 256];
        __nv_bfloat162 lo = {__float2bfloat16(v.x * inv), __float2bfloat16(v.y * inv)};
        __nv_bfloat162 hi = {__float2bfloat16(v.z * inv), __float2bfloat16(v.w * inv)};
        op[(threadIdx.x + i * 256) * 2]     = lo;
        op[(threadIdx.x + i * 256) * 2 + 1] = hi;
    }
}

// ---------------- mma helpers ----------------
__device__ __forceinline__ void ldsm4(unsigned* r, unsigned addr) {
    asm volatile("ldmatrix.sync.aligned.m8n8.x4.shared.b16 {%0,%1,%2,%3},[%4];"
                 : "=r"(r[0]), "=r"(r[1]), "=r"(r[2]), "=r"(r[3]) : "r"(addr));
}
__device__ __forceinline__ void mma16816(float* c, const unsigned* a, const unsigned* b) {
    asm volatile("mma.sync.aligned.m16n8k16.row.col.f32.bf16.bf16.f32 "
                 "{%0,%1,%2,%3},{%4,%5,%6,%7},{%8,%9},{%0,%1,%2,%3};"
                 : "+f"(c[0]), "+f"(c[1]), "+f"(c[2]), "+f"(c[3])
                 : "r"(a[0]), "r"(a[1]), "r"(a[2]), "r"(a[3]), "r"(b[0]), "r"(b[1]));
}
__device__ __forceinline__ void cpasync16(unsigned s, const void* g) {
    asm volatile("cp.async.cg.shared.global [%0], [%1], 16;" :: "r"(s), "l"(g));
}
#define CP_COMMIT() asm volatile("cp.async.commit_group;")
#define CP_WAIT1()  asm volatile("cp.async.wait_group 1;")
#define CP_WAIT0()  asm volatile("cp.async.wait_group 0;")

__device__ __forceinline__ unsigned swz(int row, int ch) {
    int o = row * 128 + ch * 16;
    return (unsigned)(o ^ ((o >> 3) & 0x70));
}

// ---------------- TN bf16 GEMM: C = alpha * A @ B^T [+bias] [+resid] ----------------
// A: [M][K] bf16 (lda), B: [N][K] bf16 (ldb). C fp32 or bf16 (ldc).
// tile 128x128, BK=64, 256 threads (8 warps 2x4, each 64x32), cp.async double buffer.
template <int OUT_BF16>
__global__ __launch_bounds__(256) void gemm_tn_bf16(
    int M, int N, int K,
    const __nv_bfloat16* __restrict__ A, int lda, long long sA,
    const __nv_bfloat16* __restrict__ B, int ldb, long long sB,
    void* __restrict__ Cv, int ldc, long long sC,
    float alpha,
    const float* __restrict__ bias,
    const float* __restrict__ resid)
{
    __shared__ __align__(1024) __nv_bfloat16 As[2][128 * 64];
    __shared__ __align__(1024) __nv_bfloat16 Bs[2][128 * 64];

    const int t = threadIdx.x;
    const int z = blockIdx.z;
    const int m0 = blockIdx.y * 128, n0 = blockIdx.x * 128;
    A += (long long)z * sA;
    B += (long long)z * sB;

    unsigned aBase0 = (unsigned)__cvta_generic_to_shared(&As[0][0]);
    unsigned aBase1 = (unsigned)__cvta_generic_to_shared(&As[1][0]);
    unsigned bBase0 = (unsigned)__cvta_generic_to_shared(&Bs[0][0]);
    unsigned bBase1 = (unsigned)__cvta_generic_to_shared(&Bs[1][0]);

    const int lrow = t >> 3;          // 0..31 (x4 iters -> 128 rows)
    const int lch  = t & 7;           // 16B chunk within 128B row

    const int warp = t >> 5;
    const int wm = warp >> 2;         // 0..1
    const int wn = warp & 3;          // 0..3
    const int lane = t & 31;
    const int lrow16 = lane & 15;     // ldmatrix row
    const int lhalf  = lane >> 4;     // ldmatrix chunk half

    float acc[4][4][4];
    #pragma unroll
    for (int i = 0; i < 4; i++)
        #pragma unroll
        for (int j = 0; j < 4; j++)
            #pragma unroll
            for (int v = 0; v < 4; v++) acc[i][j][v] = 0.0f;

    const int T = K >> 6;

    // prefetch tile 0
    {
        unsigned aB = aBase0, bB = bBase0;
        #pragma unroll
        for (int i = 0; i < 4; i++) {
            int row = lrow + i * 32;
            cpasync16(aB + swz(row, lch), A + (long long)(m0 + row) * lda + lch * 8);
            cpasync16(bB + swz(row, lch), B + (long long)(n0 + row) * ldb + lch * 8);
        }
        CP_COMMIT();
    }

    for (int kt = 0; kt < T; kt++) {
        if (kt + 1 < T) {
            unsigned aB = (kt & 1) ? aBase0 : aBase1;
            unsigned bB = (kt & 1) ? bBase0 : bBase1;
            long long ko = (long long)(kt + 1) * 64 + lch * 8;
            #pragma unroll
            for (int i = 0; i < 4; i++) {
                int row = lrow + i * 32;
                cpasync16(aB + swz(row, lch), A + (long long)(m0 + row) * lda + ko);
                cpasync16(bB + swz(row, lch), B + (long long)(n0 + row) * ldb + ko);
            }
            CP_COMMIT();
            CP_WAIT1();
        } else {
            CP_WAIT0();
        }
        __syncthreads();

        unsigned aB = (kt & 1) ? aBase1 : aBase0;
        unsigned bB = (kt & 1) ? bBase1 : bBase0;

        #pragma unroll
        for (int ks = 0; ks < 4; ks++) {
            unsigned afrag[4][4], bfrag[2][4];
            #pragma unroll
            for (int mi = 0; mi < 4; mi++) {
                int row = wm * 64 + mi * 16 + lrow16;
                ldsm4(afrag[mi], aB + swz(row, ks * 2 + lhalf));
            }
            #pragma unroll
            for (int p = 0; p < 2; p++) {
                int row = wn * 32 + p * 16 + lrow16;
                ldsm4(bfrag[p], bB + swz(row, ks * 2 + lhalf));
            }
            #pragma unroll
            for (int mi = 0; mi < 4; mi++) {
                #pragma unroll
                for (int ni = 0; ni < 4; ni++) {
                    unsigned bops[2];
                    bops[0] = bfrag[ni >> 1][ni & 1];
                    bops[1] = bfrag[ni >> 1][2 + (ni & 1)];
                    mma16816(acc[mi][ni], afrag[mi], bops);
                }
            }
        }
        __syncthreads();
    }

    // ---------------- epilogue ----------------
    const int g = lane >> 2, tig = lane & 3;
    #pragma unroll
    for (int mi = 0; mi < 4; mi++) {
        #pragma unroll
        for (int ni = 0; ni < 4; ni++) {
            int col = n0 + wn * 32 + ni * 8 + tig * 2;
            float b0 = 0.0f, b1 = 0.0f;
            if (bias) { b0 = bias[col]; b1 = bias[col + 1]; }
            #pragma unroll
            for (int half = 0; half < 2; half++) {
                long long row = (long long)(m0 + wm * 64 + mi * 16 + g + half * 8) + (long long)z * 0;
                float v0 = acc[mi][ni][half * 2]     * alpha + b0;
                float v1 = acc[mi][ni][half * 2 + 1] * alpha + b1;
                if (resid) {
                    const float* rp = resid + row * ldc + col;
                    v0 += rp[0]; v1 += rp[1];
                }
                if (OUT_BF16) {
                    __nv_bfloat16* C = (__nv_bfloat16*)Cv + (long long)z * sC;
                    __nv_bfloat162 pv = {__float2bfloat16(v0), __float2bfloat16(v1)};
                    *(__nv_bfloat162*)(C + row * ldc + col) = pv;
                } else {
                    float* C = (float*)Cv + (long long)z * sC;
                    float2 pv = {v0, v1};
                    *(float2*)(C + row * ldc + col) = pv;
                }
            }
        }
    }
}

// ---------------- launch ----------------
extern "C" void kernel_launch(void* const* d_in, const int* in_sizes, int n_in,
                              void* d_out, int out_size) {
    const float* x      = (const float*)d_in[0];
    const float* g_norm = (const float*)d_in[1];
    const float* w_qkv  = (const float*)d_in[2];
    const float* b_qkv  = (const float*)d_in[3];
    const float* w_proj = (const float*)d_in[4];
    const float* b_proj = (const float*)d_in[5];
    float* out = (float*)d_out;

    void *pqkv, *psc, *pattn, *ph, *pq, *pk, *pv, *pav, *pwq, *pwp;
    cudaGetSymbolAddress(&pqkv, g_qkv);
    cudaGetSymbolAddress(&psc, g_scores);
    cudaGetSymbolAddress(&pattn, g_attnbf);
    cudaGetSymbolAddress(&ph, g_hbf);
    cudaGetSymbolAddress(&pq, g_qbf);
    cudaGetSymbolAddress(&pk, g_kbf);
    cudaGetSymbolAddress(&pv, g_vT);
    cudaGetSymbolAddress(&pav, g_avbf);
    cudaGetSymbolAddress(&pwq, g_wqkvT);
    cudaGetSymbolAddress(&pwp, g_wprojT);
    float* qkv    = (float*)pqkv;
    float* scores = (float*)psc;
    __nv_bfloat16* attn  = (__nv_bfloat16*)pattn;
    __nv_bfloat16* hbf   = (__nv_bfloat16*)ph;
    __nv_bfloat16* qbf   = (__nv_bfloat16*)pq;
    __nv_bfloat16* kbf   = (__nv_bfloat16*)pk;
    __nv_bfloat16* vT    = (__nv_bfloat16*)pv;
    __nv_bfloat16* avbf  = (__nv_bfloat16*)pav;
    __nv_bfloat16* wqkvT = (__nv_bfloat16*)pwq;
    __nv_bfloat16* wprojT= (__nv_bfloat16*)pwp;

    // 1) ternary rope tables
    build_tables_kernel<<<(SS * HALF + 255) / 256, 256>>>();

    // 2) weight transposes -> bf16 [N][K]
    transpose_cvt_kernel<<<dim3(TD / 32, DD / 32, 1), 256>>>(
        w_qkv, 0LL, TD, wqkvT, 0LL, DD, DD, TD);
    transpose_cvt_kernel<<<dim3(DD / 32, DD / 32, 1), 256>>>(
        w_proj, 0LL, DD, wprojT, 0LL, DD, DD, DD);

    // 3) rmsnorm -> bf16
    rmsnorm_kernel<<<BB * SS, 256>>>(x, g_norm, hbf);

    // 4) qkv = h @ w_qkv + b_qkv  (fp32 out)
    gemm_tn_bf16<0><<<dim3(TD / 128, (BB * SS) / 128, 1), 256>>>(
        BB * SS, TD, DD,
        hbf, DD, 0LL,
        wqkvT, DD, 0LL,
        qkv, TD, 0LL,
        1.0f, b_qkv, nullptr);

    // 5) rope -> qbf, kbf ; transpose V -> vT bf16 [b][d][t]
    rope_kernel<<<BB * SS, 512>>>(qkv, qbf, kbf);
    transpose_cvt_kernel<<<dim3(DD / 32, SS / 32, BB), 256>>>(
        qkv + 2 * DD, (long long)SS * TD, TD,
        vT, (long long)DD * SS, SS, SS, DD);

    // 6) scores = scale * Q @ K^T (fp32 out)
    gemm_tn_bf16<0><<<dim3(SS / 128, SS / 128, BB), 256>>>(
        SS, SS, DD,
        qbf, DD, (long long)SS * DD,
        kbf, DD, (long long)SS * DD,
        scores, SS, (long long)SS * SS,
        1.0f / 32.0f, nullptr, nullptr);

    // 7) base-3 softmax -> bf16 attn
    softmax3_kernel<<<BB * SS, 256>>>(scores, attn);

    // 8) attnv = attn @ V  -> bf16  (B = vT [d][t], TN form)
    gemm_tn_bf16<1><<<dim3(DD / 128, SS / 128, BB), 256>>>(
        SS, DD, SS,
        attn, SS, (long long)SS * SS,
        vT, SS, (long long)DD * SS,
        avbf, DD, (long long)SS * DD,
        1.0f, nullptr, nullptr);

    // 9) out = attnv @ w_proj + b_proj + x (fp32 out)
    gemm_tn_bf16<0><<<dim3(DD / 128, (BB * SS) / 128, 1), 256>>>(
        BB * SS, DD, DD,
        avbf, DD, 0LL,
        wprojT, DD, 0LL,
        out, DD, 0LL,
        1.0f, b_proj, x);
}

// round 4
// speedup vs baseline: 5.2967x; 1.0479x over previous
#include <cuda_runtime.h>
#include <cuda_bf16.h>
#include <math.h>

#define BB 4
#define SS 4096
#define DD 1024
#define HALF (DD/2)
#define TD (3*DD)

// ---------------- scratch (device globals; no allocation allowed) ----------------
__device__ __align__(16) float          g_qkv[(long long)BB*SS*TD];     // 192MB fp32
__device__ __align__(16) float          g_scores[(long long)BB*SS*SS];  // 256MB fp32
__device__ __align__(16) __nv_bfloat16  g_attnbf[(long long)BB*SS*SS];  // 128MB
__device__ __align__(16) __nv_bfloat16  g_hbf[(long long)BB*SS*DD];     // 32MB
__device__ __align__(16) __nv_bfloat16  g_qbf[(long long)BB*SS*DD];     // 32MB
__device__ __align__(16) __nv_bfloat16  g_kbf[(long long)BB*SS*DD];     // 32MB
__device__ __align__(16) __nv_bfloat16  g_vT[(long long)BB*DD*SS];      // 32MB [b][d][t]
__device__ __align__(16) __nv_bfloat16  g_avbf[(long long)BB*SS*DD];    // 32MB
__device__ __align__(16) __nv_bfloat16  g_wqkvT[(long long)TD*DD];      // 6MB  [n][k]
__device__ __align__(16) __nv_bfloat16  g_wprojT[(long long)DD*DD];     // 2MB  [n][k]
__device__ signed char g_cos[SS*HALF];
__device__ signed char g_sin[SS*HALF];

// ---------------- ternary rope tables (exact fp32 chain, double trig) ----------------
__global__ void build_tables_kernel() {
    int idx = blockIdx.x * blockDim.x + threadIdx.x;
    if (idx >= SS * HALF) return;
    int s = idx / HALF;
    int j = idx - s * HALF;
    float e = (float)j / (float)HALF;
    float p = (float)pow(10000.0, (double)e);
    float invf = 1.0f / p;
    float ang = (float)s * invf;
    double c, sn;
    sincos((double)ang, &sn, &c);
    g_cos[idx] = (signed char)lrint(c);
    g_sin[idx] = (signed char)lrint(sn);
}

// ---------------- reductions ----------------
__device__ __forceinline__ float block_reduce_sum(float v, float* red) {
    int lane = threadIdx.x & 31, w = threadIdx.x >> 5;
    #pragma unroll
    for (int o = 16; o; o >>= 1) v += __shfl_xor_sync(0xffffffffu, v, o);
    if (lane == 0) red[w] = v;
    __syncthreads();
    if (w == 0) {
        v = (lane < (int)(blockDim.x >> 5)) ? red[lane] : 0.0f;
        #pragma unroll
        for (int o = 16; o; o >>= 1) v += __shfl_xor_sync(0xffffffffu, v, o);
        if (lane == 0) red[0] = v;
    }
    __syncthreads();
    float out = red[0];
    __syncthreads();
    return out;
}
__device__ __forceinline__ float block_reduce_max(float v, float* red) {
    int lane = threadIdx.x & 31, w = threadIdx.x >> 5;
    #pragma unroll
    for (int o = 16; o; o >>= 1) v = fmaxf(v, __shfl_xor_sync(0xffffffffu, v, o));
    if (lane == 0) red[w] = v;
    __syncthreads();
    if (w == 0) {
        v = (lane < (int)(blockDim.x >> 5)) ? red[lane] : -INFINITY;
        #pragma unroll
        for (int o = 16; o; o >>= 1) v = fmaxf(v, __shfl_xor_sync(0xffffffffu, v, o));
        if (lane == 0) red[0] = v;
    }
    __syncthreads();
    float out = red[0];
    __syncthreads();
    return out;
}

// ---------------- rmsnorm -> bf16 ----------------
__global__ __launch_bounds__(256) void rmsnorm_kernel(const float* __restrict__ x,
                                                      const float* __restrict__ g,
                                                      __nv_bfloat16* __restrict__ h) {
    __shared__ float red[32];
    long long base = (long long)blockIdx.x * DD;
    float4 v = *(const float4*)(x + base + (long long)threadIdx.x * 4);
    float ss = v.x*v.x + v.y*v.y + v.z*v.z + v.w*v.w;
    float total = block_reduce_sum(ss, red);
    float r = rsqrtf(total * (1.0f / DD) + 1e-6f);
    float4 gv = *(const float4*)(g + (long long)threadIdx.x * 4);
    __nv_bfloat162 o0 = {__float2bfloat16(v.x*r*gv.x), __float2bfloat16(v.y*r*gv.y)};
    __nv_bfloat162 o1 = {__float2bfloat16(v.z*r*gv.z), __float2bfloat16(v.w*r*gv.w)};
    __nv_bfloat162* hp = (__nv_bfloat162*)(h + base + (long long)threadIdx.x * 4);
    hp[0] = o0; hp[1] = o1;
}

// ---------------- transpose + convert f32 -> bf16 ----------------
__global__ __launch_bounds__(256) void transpose_cvt_kernel(
    const float* __restrict__ in, long long sIn, int ldin,
    __nv_bfloat16* __restrict__ out, long long sOut, int ldout,
    int R, int C)
{
    __shared__ float tile[32][33];
    int z = blockIdx.z;
    int r0 = blockIdx.y * 32, c0 = blockIdx.x * 32;
    int tx = threadIdx.x & 31, ty = threadIdx.x >> 5;
    const float* ip = in + (long long)z * sIn;
    #pragma unroll
    for (int i = 0; i < 4; i++) {
        int r = r0 + ty + i * 8;
        tile[ty + i * 8][tx] = ip[(long long)r * ldin + c0 + tx];
    }
    __syncthreads();
    __nv_bfloat16* op = out + (long long)z * sOut;
    #pragma unroll
    for (int i = 0; i < 4; i++) {
        int c = c0 + ty + i * 8;
        op[(long long)c * ldout + r0 + tx] = __float2bfloat16(tile[tx][ty + i * 8]);
    }
}

// ---------------- rope: qkv fp32 -> qbf, kbf bf16 ----------------
__global__ __launch_bounds__(512) void rope_kernel(const float* __restrict__ qkv,
                                                   __nv_bfloat16* __restrict__ qo,
                                                   __nv_bfloat16* __restrict__ ko) {
    int bs = blockIdx.x;
    int s = bs & (SS - 1);
    int j = threadIdx.x;
    float c  = (float)g_cos[s * HALF + j];
    float sn = (float)g_sin[s * HALF + j];
    const float* q = qkv + (long long)bs * TD;
    const float* k = q + DD;
    long long ob = (long long)bs * DD;
    float a = q[j], b = q[j + HALF];
    qo[ob + j]        = __float2bfloat16(a * c - b * sn);
    qo[ob + j + HALF] = __float2bfloat16(b * c + a * sn);
    a = k[j]; b = k[j + HALF];
    ko[ob + j]        = __float2bfloat16(a * c - b * sn);
    ko[ob + j + HALF] = __float2bfloat16(b * c + a * sn);
}

// ---------------- base-3 softmax: f32 scores -> bf16 attn ----------------
__global__ __launch_bounds__(256) void softmax3_kernel(const float* __restrict__ sc,
                                                       __nv_bfloat16* __restrict__ attn) {
    __shared__ __align__(16) float buf[SS];
    __shared__ float red[32];
    long long base = (long long)blockIdx.x * SS;
    const float4* gp = (const float4*)(sc + base);
    float4* sb = (float4*)buf;
    float m = -INFINITY;
    #pragma unroll
    for (int i = 0; i < 4; i++) {
        float4 v = gp[threadIdx.x + i * 256];
        sb[threadIdx.x + i * 256] = v;
        m = fmaxf(m, fmaxf(fmaxf(v.x, v.y), fmaxf(v.z, v.w)));
    }
    m = block_reduce_max(m, red);
    const float L23 = 1.5849625007211562f;
    float sum = 0.0f;
    #pragma unroll
    for (int i = 0; i < 4; i++) {
        float4 v = sb[threadIdx.x + i * 256];
        v.x = exp2f((v.x - m) * L23); v.y = exp2f((v.y - m) * L23);
        v.z = exp2f((v.z - m) * L23); v.w = exp2f((v.w - m) * L23);
        sb[threadIdx.x + i * 256] = v;
        sum += v.x + v.y + v.z + v.w;
    }
    sum = block_reduce_sum(sum, red);
    float inv = 1.0f / sum;
    __nv_bfloat162* op = (__nv_bfloat162*)(attn + base);
    #pragma unroll
    for (int i = 0; i < 4; i++) {
        float4 v = sb[threadIdx.x + i * 256];
        __nv_bfloat162 lo = {__float2bfloat16(v.x * inv), __float2bfloat16(v.y * inv)};
        __nv_bfloat162 hi = {__float2bfloat16(v.z * inv), __float2bfloat16(v.w * inv)};
        op[(threadIdx.x + i * 256) * 2]     = lo;
        op[(threadIdx.x + i * 256) * 2 + 1] = hi;
    }
}

// ---------------- mma helpers ----------------
__device__ __forceinline__ void ldsm4(unsigned* r, unsigned addr) {
    asm volatile("ldmatrix.sync.aligned.m8n8.x4.shared.b16 {%0,%1,%2,%3},[%4];"
                 : "=r"(r[0]), "=r"(r[1]), "=r"(r[2]), "=r"(r[3]) : "r"(addr));
}
__device__ __forceinline__ void mma16816(float* c, const unsigned* a, unsigned b0, unsigned b1) {
    asm volatile("mma.sync.aligned.m16n8k16.row.col.f32.bf16.bf16.f32 "
                 "{%0,%1,%2,%3},{%4,%5,%6,%7},{%8,%9},{%0,%1,%2,%3};"
                 : "+f"(c[0]), "+f"(c[1]), "+f"(c[2]), "+f"(c[3])
                 : "r"(a[0]), "r"(a[1]), "r"(a[2]), "r"(a[3]), "r"(b0), "r"(b1));
}
__device__ __forceinline__ void cpasync16(unsigned s, const void* g) {
    asm volatile("cp.async.cg.shared.global [%0], [%1], 16;" :: "r"(s), "l"(g));
}
#define CP_COMMIT() asm volatile("cp.async.commit_group;" ::: "memory")

__device__ __forceinline__ unsigned swz(int row, int ch) {
    int o = row * 128 + ch * 16;
    return (unsigned)(o ^ ((o >> 3) & 0x70));
}

// ================= TN bf16 GEMM: C = alpha*A@B^T [+bias] [+resid] =================
// A [M][K] bf16 (lda), B [N][K] bf16 (ldb). Tile 128x256, BK=64, 3-stage cp.async,
// 256 threads = 8 warps (2x4), each warp 64x64, double-buffered ldmatrix frags.
#define STG 49152u   // per stage: A 16KB + B 32KB
template <int OUT_BF16>
__global__ __launch_bounds__(256) void gemm_tn_bf16(
    int K,
    const __nv_bfloat16* __restrict__ A, int lda, long long sA,
    const __nv_bfloat16* __restrict__ B, int ldb, long long sB,
    void* __restrict__ Cv, int ldc, long long sC,
    float alpha,
    const float* __restrict__ bias,
    const float* __restrict__ resid)
{
    extern __shared__ __align__(1024) char dsm[];
    unsigned sbase = (unsigned)__cvta_generic_to_shared(dsm);

    const int t = threadIdx.x;
    const int z = blockIdx.z;
    const int m0 = blockIdx.y * 128, n0 = blockIdx.x * 256;
    A += (long long)z * sA + (long long)m0 * lda;
    B += (long long)z * sB + (long long)n0 * ldb;

    const int lrow = t >> 3;          // 0..31
    const int lch  = t & 7;           // 16B chunk in 128B row

    const int warp = t >> 5;
    const int wm = warp >> 2;         // 0..1  (row 64-half)
    const int wn = warp & 3;          // 0..3  (col 64-quarter)
    const int lane = t & 31;
    const int lrow16 = lane & 15;
    const int lhalf  = lane >> 4;

    float acc[4][8][4];
    #pragma unroll
    for (int i = 0; i < 4; i++)
        #pragma unroll
        for (int j = 0; j < 8; j++)
            #pragma unroll
            for (int v = 0; v < 4; v++) acc[i][j][v] = 0.0f;

    const int T = K >> 6;

    // prefetch stages 0,1
    #pragma unroll
    for (int c = 0; c < 2; c++) {
        unsigned aB = sbase + c * STG;
        unsigned bB = aB + 16384u;
        long long ko = (long long)c * 64 + lch * 8;
        #pragma unroll
        for (int i = 0; i < 4; i++)
            cpasync16(aB + swz(lrow + i * 32, lch), A + (long long)(lrow + i * 32) * lda + ko);
        #pragma unroll
        for (int i = 0; i < 8; i++)
            cpasync16(bB + swz(lrow + i * 32, lch), B + (long long)(lrow + i * 32) * ldb + ko);
        CP_COMMIT();
    }

    int s = 0;
    for (int kt = 0; kt < T; kt++) {
        if (kt + 1 < T) {
            asm volatile("cp.async.wait_group 1;" ::: "memory");
        } else {
            asm volatile("cp.async.wait_group 0;" ::: "memory");
        }
        __syncthreads();

        // issue prefetch for kt+2 into the stage just freed (compute of kt-1 done)
        if (kt + 2 < T) {
            int c = kt + 2;
            int sp = (s + 2) % 3;
            unsigned aB = sbase + sp * STG;
            unsigned bB = aB + 16384u;
            long long ko = (long long)c * 64 + lch * 8;
            #pragma unroll
            for (int i = 0; i < 4; i++)
                cpasync16(aB + swz(lrow + i * 32, lch), A + (long long)(lrow + i * 32) * lda + ko);
            #pragma unroll
            for (int i = 0; i < 8; i++)
                cpasync16(bB + swz(lrow + i * 32, lch), B + (long long)(lrow + i * 32) * ldb + ko);
            CP_COMMIT();
        }

        unsigned aB = sbase + s * STG;
        unsigned bB = aB + 16384u;

        unsigned afrag[2][4][4], bfrag[2][4][4];
        // preload ks=0 frags
        #pragma unroll
        for (int mi = 0; mi < 4; mi++)
            ldsm4(afrag[0][mi], aB + swz(wm * 64 + mi * 16 + lrow16, lhalf));
        #pragma unroll
        for (int p = 0; p < 4; p++)
            ldsm4(bfrag[0][p], bB + swz(wn * 64 + p * 16 + lrow16, lhalf));

        #pragma unroll
        for (int ks = 0; ks < 4; ks++) {
            int cur = ks & 1, nxt = cur ^ 1;
            if (ks < 3) {
                #pragma unroll
                for (int mi = 0; mi < 4; mi++)
                    ldsm4(afrag[nxt][mi], aB + swz(wm * 64 + mi * 16 + lrow16, (ks + 1) * 2 + lhalf));
                #pragma unroll
                for (int p = 0; p < 4; p++)
                    ldsm4(bfrag[nxt][p], bB + swz(wn * 64 + p * 16 + lrow16, (ks + 1) * 2 + lhalf));
            }
            #pragma unroll
            for (int mi = 0; mi < 4; mi++) {
                #pragma unroll
                for (int ni = 0; ni < 8; ni++) {
                    const unsigned* bf = bfrag[cur][ni >> 1];
                    mma16816(acc[mi][ni], afrag[cur][mi], bf[ni & 1], bf[2 + (ni & 1)]);
                }
            }
        }
        __syncthreads();
        s = (s + 1) % 3;
    }

    // ---------------- epilogue ----------------
    const int g = lane >> 2, tig = lane & 3;
    #pragma unroll
    for (int mi = 0; mi < 4; mi++) {
        #pragma unroll
        for (int ni = 0; ni < 8; ni++) {
            int col = n0 + wn * 64 + ni * 8 + tig * 2;
            float b0 = 0.0f, b1 = 0.0f;
            if (bias) { b0 = bias[col]; b1 = bias[col + 1]; }
            #pragma unroll
            for (int half = 0; half < 2; half++) {
                long long row = (long long)(m0 + wm * 64 + mi * 16 + g + half * 8);
                float v0 = acc[mi][ni][half * 2]     * alpha + b0;
                float v1 = acc[mi][ni][half * 2 + 1] * alpha + b1;
                if (resid) {
                    const float* rp = resid + row * ldc + col;
                    v0 += rp[0]; v1 += rp[1];
                }
                if (OUT_BF16) {
                    __nv_bfloat16* C = (__nv_bfloat16*)Cv + (long long)z * sC;
                    __nv_bfloat162 pv = {__float2bfloat16(v0), __float2bfloat16(v1)};
                    *(__nv_bfloat162*)(C + row * ldc + col) = pv;
                } else {
                    float* C = (float*)Cv + (long long)z * sC;
                    float2 pv = {v0, v1};
                    *(float2*)(C + row * ldc + col) = pv;
                }
            }
        }
    }
}

// ---------------- launch ----------------
extern "C" void kernel_launch(void* const* d_in, const int* in_sizes, int n_in,
                              void* d_out, int out_size) {
    const float* x      = (const float*)d_in[0];
    const float* g_norm = (const float*)d_in[1];
    const float* w_qkv  = (const float*)d_in[2];
    const float* b_qkv  = (const float*)d_in[3];
    const float* w_proj = (const float*)d_in[4];
    const float* b_proj = (const float*)d_in[5];
    float* out = (float*)d_out;

    void *pqkv, *psc, *pattn, *ph, *pq, *pk, *pv, *pav, *pwq, *pwp;
    cudaGetSymbolAddress(&pqkv, g_qkv);
    cudaGetSymbolAddress(&psc, g_scores);
    cudaGetSymbolAddress(&pattn, g_attnbf);
    cudaGetSymbolAddress(&ph, g_hbf);
    cudaGetSymbolAddress(&pq, g_qbf);
    cudaGetSymbolAddress(&pk, g_kbf);
    cudaGetSymbolAddress(&pv, g_vT);
    cudaGetSymbolAddress(&pav, g_avbf);
    cudaGetSymbolAddress(&pwq, g_wqkvT);
    cudaGetSymbolAddress(&pwp, g_wprojT);
    float* qkv    = (float*)pqkv;
    float* scores = (float*)psc;
    __nv_bfloat16* attn  = (__nv_bfloat16*)pattn;
    __nv_bfloat16* hbf   = (__nv_bfloat16*)ph;
    __nv_bfloat16* qbf   = (__nv_bfloat16*)pq;
    __nv_bfloat16* kbf   = (__nv_bfloat16*)pk;
    __nv_bfloat16* vT    = (__nv_bfloat16*)pv;
    __nv_bfloat16* avbf  = (__nv_bfloat16*)pav;
    __nv_bfloat16* wqkvT = (__nv_bfloat16*)pwq;
    __nv_bfloat16* wprojT= (__nv_bfloat16*)pwp;

    const int SMEM = 3 * (int)STG;   // 144KB
    cudaFuncSetAttribute(gemm_tn_bf16<0>, cudaFuncAttributeMaxDynamicSharedMemorySize, SMEM);
    cudaFuncSetAttribute(gemm_tn_bf16<1>, cudaFuncAttributeMaxDynamicSharedMemorySize, SMEM);

    // 1) ternary rope tables
    build_tables_kernel<<<(SS * HALF + 255) / 256, 256>>>();

    // 2) weight transposes -> bf16 [N][K]
    transpose_cvt_kernel<<<dim3(TD / 32, DD / 32, 1), 256>>>(
        w_qkv, 0LL, TD, wqkvT, 0LL, DD, DD, TD);
    transpose_cvt_kernel<<<dim3(DD / 32, DD / 32, 1), 256>>>(
        w_proj, 0LL, DD, wprojT, 0LL, DD, DD, DD);

    // 3) rmsnorm -> bf16
    rmsnorm_kernel<<<BB * SS, 256>>>(x, g_norm, hbf);

    // 4) qkv = h @ w_qkv + b_qkv  (fp32 out)
    gemm_tn_bf16<0><<<dim3(TD / 256, (BB * SS) / 128, 1), 256, SMEM>>>(
        DD,
        hbf, DD, 0LL,
        wqkvT, DD, 0LL,
        qkv, TD, 0LL,
        1.0f, b_qkv, nullptr);

    // 5) rope -> qbf, kbf ; transpose V -> vT bf16 [b][d][t]
    rope_kernel<<<BB * SS, 512>>>(qkv, qbf, kbf);
    transpose_cvt_kernel<<<dim3(DD / 32, SS / 32, BB), 256>>>(
        qkv + 2 * DD, (long long)SS * TD, TD,
        vT, (long long)DD * SS, SS, SS, DD);

    // 6) scores = scale * Q @ K^T (fp32 out)
    gemm_tn_bf16<0><<<dim3(SS / 256, SS / 128, BB), 256, SMEM>>>(
        DD,
        qbf, DD, (long long)SS * DD,
        kbf, DD, (long long)SS * DD,
        scores, SS, (long long)SS * SS,
        1.0f / 32.0f, nullptr, nullptr);

    // 7) base-3 softmax -> bf16 attn
    softmax3_kernel<<<BB * SS, 256>>>(scores, attn);

    // 8) attnv = attn @ V -> bf16 (B = vT [d][t])
    gemm_tn_bf16<1><<<dim3(DD / 256, SS / 128, BB), 256, SMEM>>>(
        SS,
        attn, SS, (long long)SS * SS,
        vT, SS, (long long)DD * SS,
        avbf, DD, (long long)SS * DD,
        1.0f, nullptr, nullptr);

    // 9) out = attnv @ w_proj + b_proj + x (fp32 out)
    gemm_tn_bf16<0><<<dim3(DD / 256, (BB * SS) / 128, 1), 256, SMEM>>>(
        DD,
        avbf, DD, 0LL,
        wprojT, DD, 0LL,
        out, DD, 0LL,
        1.0f, b_proj, x);
}

// round 5
// speedup vs baseline: 5.3558x; 1.0111x over previous
#include <cuda_runtime.h>
#include <cuda_bf16.h>
#include <math.h>

#define BB 4
#define SS 4096
#define DD 1024
#define HALF (DD/2)
#define TD (3*DD)

// ---------------- scratch (device globals; no allocation allowed) ----------------
__device__ __align__(16) __nv_bfloat16  g_qkvbf[(long long)BB*SS*TD];   // 96MB
__device__ __align__(16) __nv_bfloat16  g_P[(long long)BB*SS*SS];       // 128MB unnormalized 3^s
__device__ __align__(16) __nv_bfloat16  g_hbf[(long long)BB*SS*DD];     // 32MB
__device__ __align__(16) unsigned char  g_qf8[(long long)BB*SS*DD];     // 16MB e4m3
__device__ __align__(16) unsigned char  g_kf8[(long long)BB*SS*DD];     // 16MB e4m3
__device__ __align__(16) __nv_bfloat16  g_vT[(long long)BB*DD*SS];      // 32MB [b][d][t]
__device__ __align__(16) __nv_bfloat16  g_avbf[(long long)BB*SS*DD];    // 32MB
__device__ __align__(16) __nv_bfloat16  g_wqkvT[(long long)TD*DD];      // 6MB  [n][k]
__device__ __align__(16) __nv_bfloat16  g_wprojT[(long long)DD*DD];     // 2MB  [n][k]
__device__ float g_rden[(long long)BB*SS];                              // 64KB 1/sum
__device__ signed char g_cos[SS*HALF];
__device__ signed char g_sin[SS*HALF];

// ---------------- ternary rope tables (exact fp32 chain, double trig) ----------------
__global__ void build_tables_kernel() {
    int idx = blockIdx.x * blockDim.x + threadIdx.x;
    if (idx >= SS * HALF) return;
    int s = idx / HALF;
    int j = idx - s * HALF;
    float e = (float)j / (float)HALF;
    float p = (float)pow(10000.0, (double)e);
    float invf = 1.0f / p;
    float ang = (float)s * invf;
    double c, sn;
    sincos((double)ang, &sn, &c);
    g_cos[idx] = (signed char)lrint(c);
    g_sin[idx] = (signed char)lrint(sn);
}

// ---------------- reductions ----------------
__device__ __forceinline__ float block_reduce_sum(float v, float* red) {
    int lane = threadIdx.x & 31, w = threadIdx.x >> 5;
    #pragma unroll
    for (int o = 16; o; o >>= 1) v += __shfl_xor_sync(0xffffffffu, v, o);
    if (lane == 0) red[w] = v;
    __syncthreads();
    if (w == 0) {
        v = (lane < (int)(blockDim.x >> 5)) ? red[lane] : 0.0f;
        #pragma unroll
        for (int o = 16; o; o >>= 1) v += __shfl_xor_sync(0xffffffffu, v, o);
        if (lane == 0) red[0] = v;
    }
    __syncthreads();
    float out = red[0];
    __syncthreads();
    return out;
}

// ---------------- rmsnorm -> bf16 ----------------
__global__ __launch_bounds__(256) void rmsnorm_kernel(const float* __restrict__ x,
                                                      const float* __restrict__ g,
                                                      __nv_bfloat16* __restrict__ h) {
    __shared__ float red[32];
    long long base = (long long)blockIdx.x * DD;
    float4 v = *(const float4*)(x + base + (long long)threadIdx.x * 4);
    float ss = v.x*v.x + v.y*v.y + v.z*v.z + v.w*v.w;
    float total = block_reduce_sum(ss, red);
    float r = rsqrtf(total * (1.0f / DD) + 1e-6f);
    float4 gv = *(const float4*)(g + (long long)threadIdx.x * 4);
    __nv_bfloat162 o0 = {__float2bfloat16(v.x*r*gv.x), __float2bfloat16(v.y*r*gv.y)};
    __nv_bfloat162 o1 = {__float2bfloat16(v.z*r*gv.z), __float2bfloat16(v.w*r*gv.w)};
    __nv_bfloat162* hp = (__nv_bfloat162*)(h + base + (long long)threadIdx.x * 4);
    hp[0] = o0; hp[1] = o1;
}

// ---------------- weight transpose + convert f32 -> bf16 ----------------
__global__ __launch_bounds__(256) void transpose_cvt_kernel(
    const float* __restrict__ in, int ldin,
    __nv_bfloat16* __restrict__ out, int ldout)
{
    __shared__ float tile[32][33];
    int r0 = blockIdx.y * 32, c0 = blockIdx.x * 32;
    int tx = threadIdx.x & 31, ty = threadIdx.x >> 5;
    #pragma unroll
    for (int i = 0; i < 4; i++)
        tile[ty + i * 8][tx] = in[(long long)(r0 + ty + i * 8) * ldin + c0 + tx];
    __syncthreads();
    #pragma unroll
    for (int i = 0; i < 4; i++)
        out[(long long)(c0 + ty + i * 8) * ldout + r0 + tx] = __float2bfloat16(tile[tx][ty + i * 8]);
}

// ---------------- V transpose bf16 -> bf16: out[b][d][t] = in[b][t][2048+d] ----------------
__global__ __launch_bounds__(256) void transpose_v_kernel(
    const __nv_bfloat16* __restrict__ in, __nv_bfloat16* __restrict__ out)
{
    __shared__ __nv_bfloat16 tile[32][33];
    int z = blockIdx.z;
    int t0 = blockIdx.y * 32, d0 = blockIdx.x * 32;
    int tx = threadIdx.x & 31, ty = threadIdx.x >> 5;
    const __nv_bfloat16* ip = in + (long long)z * SS * TD + 2 * DD;
    #pragma unroll
    for (int i = 0; i < 4; i++)
        tile[ty + i * 8][tx] = ip[(long long)(t0 + ty + i * 8) * TD + d0 + tx];
    __syncthreads();
    __nv_bfloat16* op = out + (long long)z * DD * SS;
    #pragma unroll
    for (int i = 0; i < 4; i++)
        op[(long long)(d0 + ty + i * 8) * SS + t0 + tx] = tile[tx][ty + i * 8];
}

// ---------------- rope: bf16 qkv -> e4m3 q,k ----------------
__device__ __forceinline__ unsigned short cvt_e4m3x2(float lo, float hi) {
    unsigned short r;
    asm("cvt.rn.satfinite.e4m3x2.f32 %0, %1, %2;" : "=h"(r) : "f"(hi), "f"(lo));
    return r;
}
__global__ __launch_bounds__(256) void rope_kernel(const __nv_bfloat16* __restrict__ qkv,
                                                   unsigned short* __restrict__ qo,
                                                   unsigned short* __restrict__ ko) {
    int bs = blockIdx.x;
    int s = bs & (SS - 1);
    int t = threadIdx.x;           // handles cols 2t,2t+1 and 2t+512,2t+513
    int j0 = 2 * t;
    float c0 = (float)g_cos[s * HALF + j0],     s0 = (float)g_sin[s * HALF + j0];
    float c1 = (float)g_cos[s * HALF + j0 + 1], s1 = (float)g_sin[s * HALF + j0 + 1];
    const __nv_bfloat16* q = qkv + (long long)bs * TD;
    const __nv_bfloat16* k = q + DD;
    long long ob = (long long)bs * (DD / 2);   // in fp8x2 units
    #pragma unroll
    for (int w = 0; w < 2; w++) {
        const __nv_bfloat16* src = w ? k : q;
        unsigned short* dst = w ? ko : qo;
        float a0 = __bfloat162float(src[j0]),       a1 = __bfloat162float(src[j0 + 1]);
        float b0 = __bfloat162float(src[j0 + HALF]), b1 = __bfloat162float(src[j0 + HALF + 1]);
        dst[ob + t]               = cvt_e4m3x2(a0 * c0 - b0 * s0, a1 * c1 - b1 * s1);
        dst[ob + t + HALF / 2]    = cvt_e4m3x2(b0 * c0 + a0 * s0, b1 * c1 + a1 * s1);
    }
}

// ---------------- row-sum of P -> reciprocal denominator ----------------
__global__ __launch_bounds__(256) void den_kernel(const __nv_bfloat16* __restrict__ P,
                                                  float* __restrict__ rden) {
    __shared__ float red[32];
    long long base = (long long)blockIdx.x * SS;
    const uint4* p = (const uint4*)(P + base);   // 8 bf16 per uint4
    float sum = 0.0f;
    #pragma unroll
    for (int i = 0; i < 2; i++) {
        uint4 v = p[threadIdx.x + i * 256];
        unsigned vv[4] = {v.x, v.y, v.z, v.w};
        #pragma unroll
        for (int q = 0; q < 4; q++) {
            float2 f = __bfloat1622float2(*(__nv_bfloat162*)&vv[q]);
            sum += f.x + f.y;
        }
    }
    float total = block_reduce_sum(sum, red);
    if (threadIdx.x == 0) rden[blockIdx.x] = 1.0f / total;
}

// ---------------- mma helpers ----------------
__device__ __forceinline__ void ldsm4(unsigned* r, unsigned addr) {
    asm volatile("ldmatrix.sync.aligned.m8n8.x4.shared.b16 {%0,%1,%2,%3},[%4];"
                 : "=r"(r[0]), "=r"(r[1]), "=r"(r[2]), "=r"(r[3]) : "r"(addr));
}
__device__ __forceinline__ void mma_bf16(float* c, const unsigned* a, unsigned b0, unsigned b1) {
    asm volatile("mma.sync.aligned.m16n8k16.row.col.f32.bf16.bf16.f32 "
                 "{%0,%1,%2,%3},{%4,%5,%6,%7},{%8,%9},{%0,%1,%2,%3};"
                 : "+f"(c[0]), "+f"(c[1]), "+f"(c[2]), "+f"(c[3])
                 : "r"(a[0]), "r"(a[1]), "r"(a[2]), "r"(a[3]), "r"(b0), "r"(b1));
}
__device__ __forceinline__ void mma_e4m3(float* c, const unsigned* a, unsigned b0, unsigned b1) {
    asm volatile("mma.sync.aligned.m16n8k32.row.col.f32.e4m3.e4m3.f32 "
                 "{%0,%1,%2,%3},{%4,%5,%6,%7},{%8,%9},{%0,%1,%2,%3};"
                 : "+f"(c[0]), "+f"(c[1]), "+f"(c[2]), "+f"(c[3])
                 : "r"(a[0]), "r"(a[1]), "r"(a[2]), "r"(a[3]), "r"(b0), "r"(b1));
}
__device__ __forceinline__ void cpasync16(unsigned s, const void* g) {
    asm volatile("cp.async.cg.shared.global [%0], [%1], 16;" :: "r"(s), "l"(g));
}
#define CP_COMMIT() asm volatile("cp.async.commit_group;" ::: "memory")

__device__ __forceinline__ unsigned swz(int row, int ch) {
    int o = row * 128 + ch * 16;
    return (unsigned)(o ^ ((o >> 3) & 0x70));
}

// ================= TN GEMM (bf16 or e4m3 inputs): tile 128x256, 128B k-chunks =================
// A [M][K], B [N][K], K-major. Per chunk: 128 bytes of K per row.
// EPI: 0 = f32 out (+bias+resid), 1 = bf16 out (+bias), 2 = bf16 out = 3^(acc*alpha), 3 = bf16 out = acc*rowscale
#define STG 49152u
template <int IN8, int EPI>
__global__ __launch_bounds__(256) void gemm_tc(
    int T,                                    // number of 128B K-chunks
    const char* __restrict__ A, long long ldaB, long long sAB,
    const char* __restrict__ B, long long ldbB, long long sBB,
    void* __restrict__ Cv, int ldc, long long sC,
    float alpha,
    const float* __restrict__ bias,
    const float* __restrict__ resid,
    const float* __restrict__ rowscale, long long sRS)
{
    extern __shared__ __align__(1024) char dsm[];
    unsigned sbase = (unsigned)__cvta_generic_to_shared(dsm);

    const int t = threadIdx.x;
    const int z = blockIdx.z;
    const int m0 = blockIdx.y * 128, n0 = blockIdx.x * 256;
    A += z * sAB + (long long)m0 * ldaB;
    B += z * sBB + (long long)n0 * ldbB;

    const int lrow = t >> 3;
    const int lch  = t & 7;

    const int warp = t >> 5;
    const int wm = warp >> 2;
    const int wn = warp & 3;
    const int lane = t & 31;
    const int lrow16 = lane & 15;
    const int lhalf  = lane >> 4;

    float acc[4][8][4];
    #pragma unroll
    for (int i = 0; i < 4; i++)
        #pragma unroll
        for (int j = 0; j < 8; j++)
            #pragma unroll
            for (int v = 0; v < 4; v++) acc[i][j][v] = 0.0f;

    // prefetch stages 0,1
    #pragma unroll
    for (int c = 0; c < 2; c++) {
        if (c < T) {
            unsigned aB = sbase + c * STG;
            unsigned bB = aB + 16384u;
            long long ko = (long long)c * 128 + lch * 16;
            #pragma unroll
            for (int i = 0; i < 4; i++)
                cpasync16(aB + swz(lrow + i * 32, lch), A + (long long)(lrow + i * 32) * ldaB + ko);
            #pragma unroll
            for (int i = 0; i < 8; i++)
                cpasync16(bB + swz(lrow + i * 32, lch), B + (long long)(lrow + i * 32) * ldbB + ko);
        }
        CP_COMMIT();
    }

    int s = 0;
    for (int kt = 0; kt < T; kt++) {
        if (kt + 1 < T) {
            asm volatile("cp.async.wait_group 1;" ::: "memory");
        } else {
            asm volatile("cp.async.wait_group 0;" ::: "memory");
        }
        __syncthreads();

        if (kt + 2 < T) {
            int c = kt + 2;
            int sp = (s + 2) % 3;
            unsigned aB = sbase + sp * STG;
            unsigned bB = aB + 16384u;
            long long ko = (long long)c * 128 + lch * 16;
            #pragma unroll
            for (int i = 0; i < 4; i++)
                cpasync16(aB + swz(lrow + i * 32, lch), A + (long long)(lrow + i * 32) * ldaB + ko);
            #pragma unroll
            for (int i = 0; i < 8; i++)
                cpasync16(bB + swz(lrow + i * 32, lch), B + (long long)(lrow + i * 32) * ldbB + ko);
            CP_COMMIT();
        } else {
            CP_COMMIT();
        }

        unsigned aB = sbase + s * STG;
        unsigned bB = aB + 16384u;

        unsigned afrag[2][4][4], bfrag[2][4][4];
        #pragma unroll
        for (int mi = 0; mi < 4; mi++)
            ldsm4(afrag[0][mi], aB + swz(wm * 64 + mi * 16 + lrow16, lhalf));
        #pragma unroll
        for (int p = 0; p < 4; p++)
            ldsm4(bfrag[0][p], bB + swz(wn * 64 + p * 16 + lrow16, lhalf));

        #pragma unroll
        for (int ks = 0; ks < 4; ks++) {
            int cur = ks & 1, nxt = cur ^ 1;
            if (ks < 3) {
                #pragma unroll
                for (int mi = 0; mi < 4; mi++)
                    ldsm4(afrag[nxt][mi], aB + swz(wm * 64 + mi * 16 + lrow16, (ks + 1) * 2 + lhalf));
                #pragma unroll
                for (int p = 0; p < 4; p++)
                    ldsm4(bfrag[nxt][p], bB + swz(wn * 64 + p * 16 + lrow16, (ks + 1) * 2 + lhalf));
            }
            #pragma unroll
            for (int mi = 0; mi < 4; mi++) {
                #pragma unroll
                for (int ni = 0; ni < 8; ni++) {
                    const unsigned* bf = bfrag[cur][ni >> 1];
                    if (IN8) mma_e4m3(acc[mi][ni], afrag[cur][mi], bf[ni & 1], bf[2 + (ni & 1)]);
                    else     mma_bf16(acc[mi][ni], afrag[cur][mi], bf[ni & 1], bf[2 + (ni & 1)]);
                }
            }
        }
        __syncthreads();
        s = (s + 1) % 3;
    }

    // ---------------- epilogue ----------------
    const float L23 = 1.5849625007211562f; (void)L23;
    const int g = lane >> 2, tig = lane & 3;
    #pragma unroll
    for (int mi = 0; mi < 4; mi++) {
        #pragma unroll
        for (int half = 0; half < 2; half++) {
            long long row = (long long)(m0 + wm * 64 + mi * 16 + g + half * 8);
            float rs = 0.0f;
            if (EPI == 3) rs = rowscale[z * sRS + row];
            #pragma unroll
            for (int ni = 0; ni < 8; ni++) {
                int col = n0 + wn * 64 + ni * 8 + tig * 2;
                float v0 = acc[mi][ni][half * 2];
                float v1 = acc[mi][ni][half * 2 + 1];
                if (EPI == 0) {
                    v0 += bias[col] + resid[row * ldc + col];
                    v1 += bias[col + 1] + resid[row * ldc + col + 1];
                    float* C = (float*)Cv + z * sC;
                    *(float2*)(C + row * ldc + col) = make_float2(v0, v1);
                } else {
                    if (EPI == 1) { v0 += bias[col]; v1 += bias[col + 1]; }
                    if (EPI == 2) { v0 = exp2f(v0 * alpha); v1 = exp2f(v1 * alpha); }
                    if (EPI == 3) { v0 *= rs; v1 *= rs; }
                    __nv_bfloat16* C = (__nv_bfloat16*)Cv + z * sC;
                    __nv_bfloat162 pv = {__float2bfloat16(v0), __float2bfloat16(v1)};
                    *(__nv_bfloat162*)(C + row * ldc + col) = pv;
                }
            }
        }
    }
}

// ---------------- launch ----------------
extern "C" void kernel_launch(void* const* d_in, const int* in_sizes, int n_in,
                              void* d_out, int out_size) {
    const float* x      = (const float*)d_in[0];
    const float* g_norm = (const float*)d_in[1];
    const float* w_qkv  = (const float*)d_in[2];
    const float* b_qkv  = (const float*)d_in[3];
    const float* w_proj = (const float*)d_in[4];
    const float* b_proj = (const float*)d_in[5];
    float* out = (float*)d_out;

    void *pqkv, *pP, *ph, *pq, *pk, *pv, *pav, *pwq, *pwp, *prd;
    cudaGetSymbolAddress(&pqkv, g_qkvbf);
    cudaGetSymbolAddress(&pP, g_P);
    cudaGetSymbolAddress(&ph, g_hbf);
    cudaGetSymbolAddress(&pq, g_qf8);
    cudaGetSymbolAddress(&pk, g_kf8);
    cudaGetSymbolAddress(&pv, g_vT);
    cudaGetSymbolAddress(&pav, g_avbf);
    cudaGetSymbolAddress(&pwq, g_wqkvT);
    cudaGetSymbolAddress(&pwp, g_wprojT);
    cudaGetSymbolAddress(&prd, g_rden);
    __nv_bfloat16* qkvbf = (__nv_bfloat16*)pqkv;
    __nv_bfloat16* P     = (__nv_bfloat16*)pP;
    __nv_bfloat16* hbf   = (__nv_bfloat16*)ph;
    unsigned char* qf8   = (unsigned char*)pq;
    unsigned char* kf8   = (unsigned char*)pk;
    __nv_bfloat16* vT    = (__nv_bfloat16*)pv;
    __nv_bfloat16* avbf  = (__nv_bfloat16*)pav;
    __nv_bfloat16* wqkvT = (__nv_bfloat16*)pwq;
    __nv_bfloat16* wprojT= (__nv_bfloat16*)pwp;
    float* rden          = (float*)prd;

    const int SMEM = 3 * (int)STG;   // 144KB
    cudaFuncSetAttribute(gemm_tc<0,0>, cudaFuncAttributeMaxDynamicSharedMemorySize, SMEM);
    cudaFuncSetAttribute(gemm_tc<0,1>, cudaFuncAttributeMaxDynamicSharedMemorySize, SMEM);
    cudaFuncSetAttribute(gemm_tc<1,2>, cudaFuncAttributeMaxDynamicSharedMemorySize, SMEM);
    cudaFuncSetAttribute(gemm_tc<0,3>, cudaFuncAttributeMaxDynamicSharedMemorySize, SMEM);

    // 1) tables + weight transposes + rmsnorm
    build_tables_kernel<<<(SS * HALF + 255) / 256, 256>>>();
    transpose_cvt_kernel<<<dim3(TD / 32, DD / 32), 256>>>(w_qkv, TD, wqkvT, DD);
    transpose_cvt_kernel<<<dim3(DD / 32, DD / 32), 256>>>(w_proj, DD, wprojT, DD);
    rmsnorm_kernel<<<BB * SS, 256>>>(x, g_norm, hbf);

    // 2) qkv = h @ w_qkv + b_qkv  -> bf16
    gemm_tc<0,1><<<dim3(TD / 256, (BB * SS) / 128, 1), 256, SMEM>>>(
        DD * 2 / 128,
        (const char*)hbf, DD * 2, 0LL,
        (const char*)wqkvT, DD * 2, 0LL,
        qkvbf, TD, 0LL,
        1.0f, b_qkv, nullptr, nullptr, 0LL);

    // 3) rope -> q,k fp8 ; V transpose -> vT bf16
    rope_kernel<<<BB * SS, 256>>>(qkvbf, (unsigned short*)qf8, (unsigned short*)kf8);
    transpose_v_kernel<<<dim3(DD / 32, SS / 32, BB), 256>>>(qkvbf, vT);

    // 4) P = 3^(q@k^T / 32)   (fp8 inputs, bf16 out, no max needed: |s| <= 13)
    gemm_tc<1,2><<<dim3(SS / 256, SS / 128, BB), 256, SMEM>>>(
        DD / 128,
        (const char*)qf8, DD, (long long)SS * DD,
        (const char*)kf8, DD, (long long)SS * DD,
        P, SS, (long long)SS * SS,
        1.5849625007211562f / 32.0f, nullptr, nullptr, nullptr, 0LL);

    // 5) rden[row] = 1 / sum_t P[row][t]
    den_kernel<<<BB * SS, 256>>>(P, rden);

    // 6) avbf = (P @ V) * rden[row]  -> bf16
    gemm_tc<0,3><<<dim3(DD / 256, SS / 128, BB), 256, SMEM>>>(
        SS * 2 / 128,
        (const char*)P, SS * 2, (long long)SS * SS * 2,
        (const char*)vT, SS * 2, (long long)DD * SS * 2,
        avbf, DD, (long long)SS * DD,
        1.0f, nullptr, nullptr, rden, (long long)SS);

    // 7) out = avbf @ w_proj + b_proj + x  -> fp32
    gemm_tc<0,0><<<dim3(DD / 256, (BB * SS) / 128, 1), 256, SMEM>>>(
        DD * 2 / 128,
        (const char*)avbf, DD * 2, 0LL,
        (const char*)wprojT, DD * 2, 0LL,
        out, DD, 0LL,
        1.0f, b_proj, x, nullptr, 0LL);
}

// round 6
// speedup vs baseline: 5.4775x; 1.0227x over previous
#include <cuda_runtime.h>
#include <cuda_bf16.h>
#include <math.h>

#define BB 4
#define SS 4096
#define DD 1024
#define HALF (DD/2)
#define TD (3*DD)

// ---------------- scratch (device globals; no allocation allowed) ----------------
__device__ __align__(16) __nv_bfloat16  g_qkvbf[(long long)BB*SS*TD];   // 96MB
__device__ __align__(16) __nv_bfloat16  g_P[(long long)BB*SS*SS];       // 128MB unnormalized 3^s
__device__ __align__(16) __nv_bfloat16  g_hbf[(long long)BB*SS*DD];     // 32MB
__device__ __align__(16) unsigned char  g_qf8[(long long)BB*SS*DD];     // 16MB e4m3
__device__ __align__(16) unsigned char  g_kf8[(long long)BB*SS*DD];     // 16MB e4m3
__device__ __align__(16) __nv_bfloat16  g_vT[(long long)BB*DD*SS];      // 32MB [b][d][t]
__device__ __align__(16) __nv_bfloat16  g_avbf[(long long)BB*SS*DD];    // 32MB
__device__ __align__(16) __nv_bfloat16  g_wqkvT[(long long)TD*DD];      // 6MB  [n][k]
__device__ __align__(16) __nv_bfloat16  g_wprojT[(long long)DD*DD];     // 2MB  [n][k]
__device__ float g_den[(long long)BB*SS];                               // row sums of P
__device__ signed char g_cos[SS*HALF];
__device__ signed char g_sin[SS*HALF];

// ---------------- ternary rope tables (exact fp32 chain, double trig) ----------------
__global__ void build_tables_kernel() {
    int idx = blockIdx.x * blockDim.x + threadIdx.x;
    if (idx >= SS * HALF) return;
    int s = idx / HALF;
    int j = idx - s * HALF;
    float e = (float)j / (float)HALF;
    float p = (float)pow(10000.0, (double)e);
    float invf = 1.0f / p;
    float ang = (float)s * invf;
    double c, sn;
    sincos((double)ang, &sn, &c);
    g_cos[idx] = (signed char)lrint(c);
    g_sin[idx] = (signed char)lrint(sn);
}

// ---------------- zero den ----------------
__global__ void zero_den_kernel(float* __restrict__ den) {
    den[blockIdx.x * 256 + threadIdx.x] = 0.0f;
}

// ---------------- reductions ----------------
__device__ __forceinline__ float block_reduce_sum(float v, float* red) {
    int lane = threadIdx.x & 31, w = threadIdx.x >> 5;
    #pragma unroll
    for (int o = 16; o; o >>= 1) v += __shfl_xor_sync(0xffffffffu, v, o);
    if (lane == 0) red[w] = v;
    __syncthreads();
    if (w == 0) {
        v = (lane < (int)(blockDim.x >> 5)) ? red[lane] : 0.0f;
        #pragma unroll
        for (int o = 16; o; o >>= 1) v += __shfl_xor_sync(0xffffffffu, v, o);
        if (lane == 0) red[0] = v;
    }
    __syncthreads();
    float out = red[0];
    __syncthreads();
    return out;
}

// ---------------- rmsnorm -> bf16 ----------------
__global__ __launch_bounds__(256) void rmsnorm_kernel(const float* __restrict__ x,
                                                      const float* __restrict__ g,
                                                      __nv_bfloat16* __restrict__ h) {
    __shared__ float red[32];
    long long base = (long long)blockIdx.x * DD;
    float4 v = *(const float4*)(x + base + (long long)threadIdx.x * 4);
    float ss = v.x*v.x + v.y*v.y + v.z*v.z + v.w*v.w;
    float total = block_reduce_sum(ss, red);
    float r = rsqrtf(total * (1.0f / DD) + 1e-6f);
    float4 gv = *(const float4*)(g + (long long)threadIdx.x * 4);
    __nv_bfloat162 o0 = {__float2bfloat16(v.x*r*gv.x), __float2bfloat16(v.y*r*gv.y)};
    __nv_bfloat162 o1 = {__float2bfloat16(v.z*r*gv.z), __float2bfloat16(v.w*r*gv.w)};
    __nv_bfloat162* hp = (__nv_bfloat162*)(h + base + (long long)threadIdx.x * 4);
    hp[0] = o0; hp[1] = o1;
}

// ---------------- weight transpose + convert f32 -> bf16 ----------------
__global__ __launch_bounds__(256) void transpose_cvt_kernel(
    const float* __restrict__ in, int ldin,
    __nv_bfloat16* __restrict__ out, int ldout)
{
    __shared__ float tile[32][33];
    int r0 = blockIdx.y * 32, c0 = blockIdx.x * 32;
    int tx = threadIdx.x & 31, ty = threadIdx.x >> 5;
    #pragma unroll
    for (int i = 0; i < 4; i++)
        tile[ty + i * 8][tx] = in[(long long)(r0 + ty + i * 8) * ldin + c0 + tx];
    __syncthreads();
    #pragma unroll
    for (int i = 0; i < 4; i++)
        out[(long long)(c0 + ty + i * 8) * ldout + r0 + tx] = __float2bfloat16(tile[tx][ty + i * 8]);
}

// ---------------- V transpose bf16 -> bf16: out[b][d][t] = in[b][t][2048+d] ----------------
__global__ __launch_bounds__(256) void transpose_v_kernel(
    const __nv_bfloat16* __restrict__ in, __nv_bfloat16* __restrict__ out)
{
    __shared__ __nv_bfloat16 tile[32][33];
    int z = blockIdx.z;
    int t0 = blockIdx.y * 32, d0 = blockIdx.x * 32;
    int tx = threadIdx.x & 31, ty = threadIdx.x >> 5;
    const __nv_bfloat16* ip = in + (long long)z * SS * TD + 2 * DD;
    #pragma unroll
    for (int i = 0; i < 4; i++)
        tile[ty + i * 8][tx] = ip[(long long)(t0 + ty + i * 8) * TD + d0 + tx];
    __syncthreads();
    __nv_bfloat16* op = out + (long long)z * DD * SS;
    #pragma unroll
    for (int i = 0; i < 4; i++)
        op[(long long)(d0 + ty + i * 8) * SS + t0 + tx] = tile[tx][ty + i * 8];
}

// ---------------- rope: bf16 qkv -> e4m3 q,k ----------------
__device__ __forceinline__ unsigned short cvt_e4m3x2(float lo, float hi) {
    unsigned short r;
    asm("cvt.rn.satfinite.e4m3x2.f32 %0, %1, %2;" : "=h"(r) : "f"(hi), "f"(lo));
    return r;
}
__global__ __launch_bounds__(256) void rope_kernel(const __nv_bfloat16* __restrict__ qkv,
                                                   unsigned short* __restrict__ qo,
                                                   unsigned short* __restrict__ ko) {
    int bs = blockIdx.x;
    int s = bs & (SS - 1);
    int t = threadIdx.x;
    int j0 = 2 * t;
    float c0 = (float)g_cos[s * HALF + j0],     s0 = (float)g_sin[s * HALF + j0];
    float c1 = (float)g_cos[s * HALF + j0 + 1], s1 = (float)g_sin[s * HALF + j0 + 1];
    const __nv_bfloat16* q = qkv + (long long)bs * TD;
    const __nv_bfloat16* k = q + DD;
    long long ob = (long long)bs * (DD / 2);
    #pragma unroll
    for (int w = 0; w < 2; w++) {
        const __nv_bfloat16* src = w ? k : q;
        unsigned short* dst = w ? ko : qo;
        float a0 = __bfloat162float(src[j0]),        a1 = __bfloat162float(src[j0 + 1]);
        float b0 = __bfloat162float(src[j0 + HALF]), b1 = __bfloat162float(src[j0 + HALF + 1]);
        dst[ob + t]            = cvt_e4m3x2(a0 * c0 - b0 * s0, a1 * c1 - b1 * s1);
        dst[ob + t + HALF / 2] = cvt_e4m3x2(b0 * c0 + a0 * s0, b1 * c1 + a1 * s1);
    }
}

// ---------------- mma helpers ----------------
__device__ __forceinline__ void ldsm4(unsigned* r, unsigned addr) {
    asm volatile("ldmatrix.sync.aligned.m8n8.x4.shared.b16 {%0,%1,%2,%3},[%4];"
                 : "=r"(r[0]), "=r"(r[1]), "=r"(r[2]), "=r"(r[3]) : "r"(addr));
}
__device__ __forceinline__ void mma_bf16(float* c, const unsigned* a, unsigned b0, unsigned b1) {
    asm volatile("mma.sync.aligned.m16n8k16.row.col.f32.bf16.bf16.f32 "
                 "{%0,%1,%2,%3},{%4,%5,%6,%7},{%8,%9},{%0,%1,%2,%3};"
                 : "+f"(c[0]), "+f"(c[1]), "+f"(c[2]), "+f"(c[3])
                 : "r"(a[0]), "r"(a[1]), "r"(a[2]), "r"(a[3]), "r"(b0), "r"(b1));
}
__device__ __forceinline__ void mma_e4m3(float* c, const unsigned* a, unsigned b0, unsigned b1) {
    asm volatile("mma.sync.aligned.m16n8k32.row.col.f32.e4m3.e4m3.f32 "
                 "{%0,%1,%2,%3},{%4,%5,%6,%7},{%8,%9},{%0,%1,%2,%3};"
                 : "+f"(c[0]), "+f"(c[1]), "+f"(c[2]), "+f"(c[3])
                 : "r"(a[0]), "r"(a[1]), "r"(a[2]), "r"(a[3]), "r"(b0), "r"(b1));
}
__device__ __forceinline__ void cpasync16(unsigned s, const void* g) {
    asm volatile("cp.async.cg.shared.global [%0], [%1], 16;" :: "r"(s), "l"(g));
}
#define CP_COMMIT() asm volatile("cp.async.commit_group;" ::: "memory")

__device__ __forceinline__ unsigned swz(int row, int ch) {
    int o = row * 128 + ch * 16;
    return (unsigned)(o ^ ((o >> 3) & 0x70));
}

// ================= TN GEMM (bf16 or e4m3 inputs): tile 128x256, 128B k-chunks =================
// EPI: 0 = f32 out (+bias+resid), 1 = bf16 out (+bias),
//      2 = bf16 out = 3^(acc*alpha) + fused row-sum atomics into dptr,
//      3 = bf16 out = acc / dptr[row]
#define STG 49152u
template <int IN8, int EPI>
__global__ __launch_bounds__(256) void gemm_tc(
    int T,
    const char* __restrict__ A, long long ldaB, long long sAB,
    const char* __restrict__ B, long long ldbB, long long sBB,
    void* __restrict__ Cv, int ldc, long long sC,
    float alpha,
    const float* __restrict__ bias,
    const float* __restrict__ resid,
    float* __restrict__ dptr, long long sRS)
{
    extern __shared__ __align__(1024) char dsm[];
    unsigned sbase = (unsigned)__cvta_generic_to_shared(dsm);

    const int t = threadIdx.x;
    const int z = blockIdx.z;
    const int m0 = blockIdx.y * 128, n0 = blockIdx.x * 256;
    A += z * sAB + (long long)m0 * ldaB;
    B += z * sBB + (long long)n0 * ldbB;

    const int lrow = t >> 3;
    const int lch  = t & 7;

    const int warp = t >> 5;
    const int wm = warp >> 2;
    const int wn = warp & 3;
    const int lane = t & 31;
    const int lrow16 = lane & 15;
    const int lhalf  = lane >> 4;

    float acc[4][8][4];
    #pragma unroll
    for (int i = 0; i < 4; i++)
        #pragma unroll
        for (int j = 0; j < 8; j++)
            #pragma unroll
            for (int v = 0; v < 4; v++) acc[i][j][v] = 0.0f;

    // prefetch stages 0,1
    #pragma unroll
    for (int c = 0; c < 2; c++) {
        if (c < T) {
            unsigned aB = sbase + c * STG;
            unsigned bB = aB + 16384u;
            long long ko = (long long)c * 128 + lch * 16;
            #pragma unroll
            for (int i = 0; i < 4; i++)
                cpasync16(aB + swz(lrow + i * 32, lch), A + (long long)(lrow + i * 32) * ldaB + ko);
            #pragma unroll
            for (int i = 0; i < 8; i++)
                cpasync16(bB + swz(lrow + i * 32, lch), B + (long long)(lrow + i * 32) * ldbB + ko);
        }
        CP_COMMIT();
    }

    int s = 0;
    for (int kt = 0; kt < T; kt++) {
        if (kt + 1 < T) {
            asm volatile("cp.async.wait_group 1;" ::: "memory");
        } else {
            asm volatile("cp.async.wait_group 0;" ::: "memory");
        }
        // single barrier per chunk: guarantees (a) stage s data visible to all,
        // (b) all warps finished compute of chunk kt-1 before its stage is overwritten below
        __syncthreads();

        if (kt + 2 < T) {
            int c = kt + 2;
            int sp = (s + 2) % 3;
            unsigned aB = sbase + sp * STG;
            unsigned bB = aB + 16384u;
            long long ko = (long long)c * 128 + lch * 16;
            #pragma unroll
            for (int i = 0; i < 4; i++)
                cpasync16(aB + swz(lrow + i * 32, lch), A + (long long)(lrow + i * 32) * ldaB + ko);
            #pragma unroll
            for (int i = 0; i < 8; i++)
                cpasync16(bB + swz(lrow + i * 32, lch), B + (long long)(lrow + i * 32) * ldbB + ko);
            CP_COMMIT();
        } else {
            CP_COMMIT();
        }

        unsigned aB = sbase + s * STG;
        unsigned bB = aB + 16384u;

        unsigned afrag[2][4][4], bfrag[2][4][4];
        #pragma unroll
        for (int mi = 0; mi < 4; mi++)
            ldsm4(afrag[0][mi], aB + swz(wm * 64 + mi * 16 + lrow16, lhalf));
        #pragma unroll
        for (int p = 0; p < 4; p++)
            ldsm4(bfrag[0][p], bB + swz(wn * 64 + p * 16 + lrow16, lhalf));

        #pragma unroll
        for (int ks = 0; ks < 4; ks++) {
            int cur = ks & 1, nxt = cur ^ 1;
            if (ks < 3) {
                #pragma unroll
                for (int mi = 0; mi < 4; mi++)
                    ldsm4(afrag[nxt][mi], aB + swz(wm * 64 + mi * 16 + lrow16, (ks + 1) * 2 + lhalf));
                #pragma unroll
                for (int p = 0; p < 4; p++)
                    ldsm4(bfrag[nxt][p], bB + swz(wn * 64 + p * 16 + lrow16, (ks + 1) * 2 + lhalf));
            }
            #pragma unroll
            for (int mi = 0; mi < 4; mi++) {
                #pragma unroll
                for (int ni = 0; ni < 8; ni++) {
                    const unsigned* bf = bfrag[cur][ni >> 1];
                    if (IN8) mma_e4m3(acc[mi][ni], afrag[cur][mi], bf[ni & 1], bf[2 + (ni & 1)]);
                    else     mma_bf16(acc[mi][ni], afrag[cur][mi], bf[ni & 1], bf[2 + (ni & 1)]);
                }
            }
        }
        s = (s + 1) % 3;
    }

    // ---------------- epilogue ----------------
    const int g = lane >> 2, tig = lane & 3;
    #pragma unroll
    for (int mi = 0; mi < 4; mi++) {
        #pragma unroll
        for (int half = 0; half < 2; half++) {
            long long row = (long long)(m0 + wm * 64 + mi * 16 + g + half * 8);
            float rs = 0.0f;
            if (EPI == 3) rs = 1.0f / dptr[z * sRS + row];
            float rsum = 0.0f;
            #pragma unroll
            for (int ni = 0; ni < 8; ni++) {
                int col = n0 + wn * 64 + ni * 8 + tig * 2;
                float v0 = acc[mi][ni][half * 2];
                float v1 = acc[mi][ni][half * 2 + 1];
                if (EPI == 0) {
                    v0 += bias[col] + resid[row * ldc + col];
                    v1 += bias[col + 1] + resid[row * ldc + col + 1];
                    float* C = (float*)Cv + z * sC;
                    *(float2*)(C + row * ldc + col) = make_float2(v0, v1);
                } else {
                    if (EPI == 1) { v0 += bias[col]; v1 += bias[col + 1]; }
                    if (EPI == 2) { v0 = exp2f(v0 * alpha); v1 = exp2f(v1 * alpha); rsum += v0 + v1; }
                    if (EPI == 3) { v0 *= rs; v1 *= rs; }
                    __nv_bfloat16* C = (__nv_bfloat16*)Cv + z * sC;
                    __nv_bfloat162 pv = {__float2bfloat16(v0), __float2bfloat16(v1)};
                    *(__nv_bfloat162*)(C + row * ldc + col) = pv;
                }
            }
            if (EPI == 2) {
                rsum += __shfl_xor_sync(0xffffffffu, rsum, 1);
                rsum += __shfl_xor_sync(0xffffffffu, rsum, 2);
                if (tig == 0) atomicAdd(dptr + z * sRS + row, rsum);
            }
        }
    }
}

// ---------------- launch ----------------
extern "C" void kernel_launch(void* const* d_in, const int* in_sizes, int n_in,
                              void* d_out, int out_size) {
    const float* x      = (const float*)d_in[0];
    const float* g_norm = (const float*)d_in[1];
    const float* w_qkv  = (const float*)d_in[2];
    const float* b_qkv  = (const float*)d_in[3];
    const float* w_proj = (const float*)d_in[4];
    const float* b_proj = (const float*)d_in[5];
    float* out = (float*)d_out;

    void *pqkv, *pP, *ph, *pq, *pk, *pv, *pav, *pwq, *pwp, *pd;
    cudaGetSymbolAddress(&pqkv, g_qkvbf);
    cudaGetSymbolAddress(&pP, g_P);
    cudaGetSymbolAddress(&ph, g_hbf);
    cudaGetSymbolAddress(&pq, g_qf8);
    cudaGetSymbolAddress(&pk, g_kf8);
    cudaGetSymbolAddress(&pv, g_vT);
    cudaGetSymbolAddress(&pav, g_avbf);
    cudaGetSymbolAddress(&pwq, g_wqkvT);
    cudaGetSymbolAddress(&pwp, g_wprojT);
    cudaGetSymbolAddress(&pd, g_den);
    __nv_bfloat16* qkvbf = (__nv_bfloat16*)pqkv;
    __nv_bfloat16* P     = (__nv_bfloat16*)pP;
    __nv_bfloat16* hbf   = (__nv_bfloat16*)ph;
    unsigned char* qf8   = (unsigned char*)pq;
    unsigned char* kf8   = (unsigned char*)pk;
    __nv_bfloat16* vT    = (__nv_bfloat16*)pv;
    __nv_bfloat16* avbf  = (__nv_bfloat16*)pav;
    __nv_bfloat16* wqkvT = (__nv_bfloat16*)pwq;
    __nv_bfloat16* wprojT= (__nv_bfloat16*)pwp;
    float* den           = (float*)pd;

    const int SMEM = 3 * (int)STG;   // 144KB
    cudaFuncSetAttribute(gemm_tc<0,0>, cudaFuncAttributeMaxDynamicSharedMemorySize, SMEM);
    cudaFuncSetAttribute(gemm_tc<0,1>, cudaFuncAttributeMaxDynamicSharedMemorySize, SMEM);
    cudaFuncSetAttribute(gemm_tc<1,2>, cudaFuncAttributeMaxDynamicSharedMemorySize, SMEM);
    cudaFuncSetAttribute(gemm_tc<0,3>, cudaFuncAttributeMaxDynamicSharedMemorySize, SMEM);

    // 1) tables + weight transposes + rmsnorm + den zero
    build_tables_kernel<<<(SS * HALF + 255) / 256, 256>>>();
    transpose_cvt_kernel<<<dim3(TD / 32, DD / 32), 256>>>(w_qkv, TD, wqkvT, DD);
    transpose_cvt_kernel<<<dim3(DD / 32, DD / 32), 256>>>(w_proj, DD, wprojT, DD);
    rmsnorm_kernel<<<BB * SS, 256>>>(x, g_norm, hbf);
    zero_den_kernel<<<BB * SS / 256, 256>>>(den);

    // 2) qkv = h @ w_qkv + b_qkv  -> bf16
    gemm_tc<0,1><<<dim3(TD / 256, (BB * SS) / 128, 1), 256, SMEM>>>(
        DD * 2 / 128,
        (const char*)hbf, DD * 2, 0LL,
        (const char*)wqkvT, DD * 2, 0LL,
        qkvbf, TD, 0LL,
        1.0f, b_qkv, nullptr, nullptr, 0LL);

    // 3) rope -> q,k fp8 ; V transpose -> vT bf16
    rope_kernel<<<BB * SS, 256>>>(qkvbf, (unsigned short*)qf8, (unsigned short*)kf8);
    transpose_v_kernel<<<dim3(DD / 32, SS / 32, BB), 256>>>(qkvbf, vT);

    // 4) P = 3^(q@k^T / 32) -> bf16, fused row-sum atomics into den
    gemm_tc<1,2><<<dim3(SS / 256, SS / 128, BB), 256, SMEM>>>(
        DD / 128,
        (const char*)qf8, DD, (long long)SS * DD,
        (const char*)kf8, DD, (long long)SS * DD,
        P, SS, (long long)SS * SS,
        1.5849625007211562f / 32.0f, nullptr, nullptr, den, (long long)SS);

    // 5) avbf = (P @ V) / den[row]  -> bf16
    gemm_tc<0,3><<<dim3(DD / 256, SS / 128, BB), 256, SMEM>>>(
        SS * 2 / 128,
        (const char*)P, SS * 2, (long long)SS * SS * 2,
        (const char*)vT, SS * 2, (long long)DD * SS * 2,
        avbf, DD, (long long)SS * DD,
        1.0f, nullptr, nullptr, den, (long long)SS);

    // 6) out = avbf @ w_proj + b_proj + x  -> fp32
    gemm_tc<0,0><<<dim3(DD / 256, (BB * SS) / 128, 1), 256, SMEM>>>(
        DD * 2 / 128,
        (const char*)avbf, DD * 2, 0LL,
        (const char*)wprojT, DD * 2, 0LL,
        out, DD, 0LL,
        1.0f, b_proj, x, nullptr, 0LL);
}

// round 7
// speedup vs baseline: 6.5488x; 1.1956x over previous
#include <cuda_runtime.h>
#include <cuda_bf16.h>
#include <math.h>

#define BB 4
#define SS 4096
#define DD 1024
#define HALF (DD/2)
#define TD (3*DD)

// ---------------- scratch (device globals; no allocation allowed) ----------------
__device__ __align__(16) __nv_bfloat16  g_qkvbf[(long long)BB*SS*TD];   // 96MB
__device__ __align__(16) __nv_bfloat16  g_P[(long long)BB*SS*SS];       // 128MB unnormalized 3^s
__device__ __align__(16) __nv_bfloat16  g_hbf[(long long)BB*SS*DD];     // 32MB
__device__ __align__(16) unsigned char  g_qf8[(long long)BB*SS*DD];     // 16MB e4m3
__device__ __align__(16) unsigned char  g_kf8[(long long)BB*SS*DD];     // 16MB e4m3
__device__ __align__(16) __nv_bfloat16  g_vwT[(long long)BB*DD*SS];     // 32MB (V@Wproj)^T [b][d][s]
__device__ __align__(16) __nv_bfloat16  g_wqkvT[(long long)TD*DD];      // 6MB  [n][k]
__device__ __align__(16) __nv_bfloat16  g_wprojT[(long long)DD*DD];     // 2MB  [n][k]
__device__ float g_den[(long long)BB*SS];                               // row sums of P
__device__ float g_invf[HALF];
__device__ signed char g_cos[SS*HALF];
__device__ signed char g_sin[SS*HALF];

// ---------------- ternary rope tables ----------------
__global__ void build_inv_kernel() {
    int j = threadIdx.x;   // 512 threads
    float e = (float)j / (float)HALF;
    g_invf[j] = 1.0f / (float)pow(10000.0, (double)e);  // matches fp32 chain
}
__global__ void build_tables_kernel() {
    int idx = blockIdx.x * blockDim.x + threadIdx.x;
    if (idx >= SS * HALF) return;
    int s = idx / HALF;
    int j = idx - s * HALF;
    float ang = (float)s * g_invf[j];                    // exact fp32 value as in reference
    // exact-ish range reduction in double, then small-arg float trig
    double t = (double)ang;
    double k = rint(t * 0.15915494309189535);
    float r = (float)(t - k * 6.283185307179586);
    float c, sn;
    sincosf(r, &sn, &c);
    g_cos[idx] = (signed char)__float2int_rn(c);
    g_sin[idx] = (signed char)__float2int_rn(sn);
}

// ---------------- zero den ----------------
__global__ void zero_den_kernel(float* __restrict__ den) {
    den[blockIdx.x * 256 + threadIdx.x] = 0.0f;
}

// ---------------- reductions ----------------
__device__ __forceinline__ float block_reduce_sum(float v, float* red) {
    int lane = threadIdx.x & 31, w = threadIdx.x >> 5;
    #pragma unroll
    for (int o = 16; o; o >>= 1) v += __shfl_xor_sync(0xffffffffu, v, o);
    if (lane == 0) red[w] = v;
    __syncthreads();
    if (w == 0) {
        v = (lane < (int)(blockDim.x >> 5)) ? red[lane] : 0.0f;
        #pragma unroll
        for (int o = 16; o; o >>= 1) v += __shfl_xor_sync(0xffffffffu, v, o);
        if (lane == 0) red[0] = v;
    }
    __syncthreads();
    float out = red[0];
    __syncthreads();
    return out;
}

// ---------------- rmsnorm -> bf16 ----------------
__global__ __launch_bounds__(256) void rmsnorm_kernel(const float* __restrict__ x,
                                                      const float* __restrict__ g,
                                                      __nv_bfloat16* __restrict__ h) {
    __shared__ float red[32];
    long long base = (long long)blockIdx.x * DD;
    float4 v = *(const float4*)(x + base + (long long)threadIdx.x * 4);
    float ss = v.x*v.x + v.y*v.y + v.z*v.z + v.w*v.w;
    float total = block_reduce_sum(ss, red);
    float r = rsqrtf(total * (1.0f / DD) + 1e-6f);
    float4 gv = *(const float4*)(g + (long long)threadIdx.x * 4);
    __nv_bfloat162 o0 = {__float2bfloat16(v.x*r*gv.x), __float2bfloat16(v.y*r*gv.y)};
    __nv_bfloat162 o1 = {__float2bfloat16(v.z*r*gv.z), __float2bfloat16(v.w*r*gv.w)};
    __nv_bfloat162* hp = (__nv_bfloat162*)(h + base + (long long)threadIdx.x * 4);
    hp[0] = o0; hp[1] = o1;
}

// ---------------- weight transpose + convert f32 -> bf16 ----------------
__global__ __launch_bounds__(256) void transpose_cvt_kernel(
    const float* __restrict__ in, int ldin,
    __nv_bfloat16* __restrict__ out, int ldout)
{
    __shared__ float tile[32][33];
    int r0 = blockIdx.y * 32, c0 = blockIdx.x * 32;
    int tx = threadIdx.x & 31, ty = threadIdx.x >> 5;
    #pragma unroll
    for (int i = 0; i < 4; i++)
        tile[ty + i * 8][tx] = in[(long long)(r0 + ty + i * 8) * ldin + c0 + tx];
    __syncthreads();
    #pragma unroll
    for (int i = 0; i < 4; i++)
        out[(long long)(c0 + ty + i * 8) * ldout + r0 + tx] = __float2bfloat16(tile[tx][ty + i * 8]);
}

// ---------------- rope: bf16 qkv -> e4m3 q,k ----------------
__device__ __forceinline__ unsigned short cvt_e4m3x2(float lo, float hi) {
    unsigned short r;
    asm("cvt.rn.satfinite.e4m3x2.f32 %0, %1, %2;" : "=h"(r) : "f"(hi), "f"(lo));
    return r;
}
__global__ __launch_bounds__(256) void rope_kernel(const __nv_bfloat16* __restrict__ qkv,
                                                   unsigned short* __restrict__ qo,
                                                   unsigned short* __restrict__ ko) {
    int bs = blockIdx.x;
    int s = bs & (SS - 1);
    int t = threadIdx.x;
    int j0 = 2 * t;
    float c0 = (float)g_cos[s * HALF + j0],     s0 = (float)g_sin[s * HALF + j0];
    float c1 = (float)g_cos[s * HALF + j0 + 1], s1 = (float)g_sin[s * HALF + j0 + 1];
    const __nv_bfloat16* q = qkv + (long long)bs * TD;
    const __nv_bfloat16* k = q + DD;
    long long ob = (long long)bs * (DD / 2);
    #pragma unroll
    for (int w = 0; w < 2; w++) {
        const __nv_bfloat16* src = w ? k : q;
        unsigned short* dst = w ? ko : qo;
        float a0 = __bfloat162float(src[j0]),        a1 = __bfloat162float(src[j0 + 1]);
        float b0 = __bfloat162float(src[j0 + HALF]), b1 = __bfloat162float(src[j0 + HALF + 1]);
        dst[ob + t]            = cvt_e4m3x2(a0 * c0 - b0 * s0, a1 * c1 - b1 * s1);
        dst[ob + t + HALF / 2] = cvt_e4m3x2(b0 * c0 + a0 * s0, b1 * c1 + a1 * s1);
    }
}

// ---------------- mma helpers ----------------
__device__ __forceinline__ void ldsm4(unsigned* r, unsigned addr) {
    asm volatile("ldmatrix.sync.aligned.m8n8.x4.shared.b16 {%0,%1,%2,%3},[%4];"
                 : "=r"(r[0]), "=r"(r[1]), "=r"(r[2]), "=r"(r[3]) : "r"(addr));
}
__device__ __forceinline__ void mma_bf16(float* c, const unsigned* a, unsigned b0, unsigned b1) {
    asm volatile("mma.sync.aligned.m16n8k16.row.col.f32.bf16.bf16.f32 "
                 "{%0,%1,%2,%3},{%4,%5,%6,%7},{%8,%9},{%0,%1,%2,%3};"
                 : "+f"(c[0]), "+f"(c[1]), "+f"(c[2]), "+f"(c[3])
                 : "r"(a[0]), "r"(a[1]), "r"(a[2]), "r"(a[3]), "r"(b0), "r"(b1));
}
__device__ __forceinline__ void mma_e4m3(float* c, const unsigned* a, unsigned b0, unsigned b1) {
    asm volatile("mma.sync.aligned.m16n8k32.row.col.f32.e4m3.e4m3.f32 "
                 "{%0,%1,%2,%3},{%4,%5,%6,%7},{%8,%9},{%0,%1,%2,%3};"
                 : "+f"(c[0]), "+f"(c[1]), "+f"(c[2]), "+f"(c[3])
                 : "r"(a[0]), "r"(a[1]), "r"(a[2]), "r"(a[3]), "r"(b0), "r"(b1));
}
__device__ __forceinline__ void cpasync16(unsigned s, const void* g) {
    asm volatile("cp.async.cg.shared.global [%0], [%1], 16;" :: "r"(s), "l"(g));
}
#define CP_COMMIT() asm volatile("cp.async.commit_group;" ::: "memory")

__device__ __forceinline__ unsigned swz(int row, int ch) {
    int o = row * 128 + ch * 16;
    return (unsigned)(o ^ ((o >> 3) & 0x70));
}

// ================= persistent TN GEMM: tile 128x256, 128B k-chunks, flat chunk pipeline =================
// EPI: 1 = bf16 out (+bias), 2 = bf16 out = 3^(acc*alpha) + row-sum atomics into dptr,
//      3 = bf16 out plain,   4 = f32 out = acc/dptr[row] + bias + resid  (batched resid)
#define STG 49152u
template <int IN8, int EPI>
__global__ __launch_bounds__(256) void gemm_tc(
    int T, int gx, int gy, int gz,
    const char* __restrict__ A0, long long ldaB, long long sAB,
    const char* __restrict__ B0, long long ldbB, long long sBB,
    void* __restrict__ Cv, int ldc, long long sC,
    float alpha,
    const float* __restrict__ bias,
    const float* __restrict__ resid, long long sR,
    float* __restrict__ dptr, long long sRS)
{
    extern __shared__ __align__(1024) char dsm[];
    unsigned sbase = (unsigned)__cvta_generic_to_shared(dsm);

    const int t = threadIdx.x;
    const int G = gridDim.x;
    const int gxy = gx * gy;
    const int nt = gxy * gz;
    const int myCount = (nt - (int)blockIdx.x + G - 1) / G;
    if (myCount <= 0) return;
    const int myTotal = myCount * T;

    const int lrow = t >> 3;
    const int lch  = t & 7;
    const int warp = t >> 5;
    const int wm = warp >> 2;
    const int wn = warp & 3;
    const int lane = t & 31;
    const int lrow16 = lane & 15;
    const int lhalf  = lane >> 4;

    float acc[4][8][4];
    #pragma unroll
    for (int i = 0; i < 4; i++)
        #pragma unroll
        for (int j = 0; j < 8; j++)
            #pragma unroll
            for (int v = 0; v < 4; v++) acc[i][j][v] = 0.0f;

    // flat chunk prefetcher: chunk j belongs to tile (j/T) of this CTA, stage j%3
    auto prefetchChunk = [&](int j) {
        if (j < myTotal) {
            int i = j / T, c = j - i * T;
            int tid2 = (int)blockIdx.x + i * G;
            int z2 = tid2 / gxy; int rr = tid2 - z2 * gxy;
            int by = rr / gx, bx = rr - by * gx;
            const char* Ap = A0 + z2 * sAB + (long long)(by * 128) * ldaB;
            const char* Bp = B0 + z2 * sBB + (long long)(bx * 256) * ldbB;
            unsigned aB = sbase + (unsigned)(j % 3) * STG;
            unsigned bB = aB + 16384u;
            long long ko = (long long)c * 128 + lch * 16;
            #pragma unroll
            for (int ii = 0; ii < 4; ii++)
                cpasync16(aB + swz(lrow + ii * 32, lch), Ap + (long long)(lrow + ii * 32) * ldaB + ko);
            #pragma unroll
            for (int ii = 0; ii < 8; ii++)
                cpasync16(bB + swz(lrow + ii * 32, lch), Bp + (long long)(lrow + ii * 32) * ldbB + ko);
        }
        CP_COMMIT();
    };

    prefetchChunk(0);
    prefetchChunk(1);

    for (int i = 0; i < myCount; i++) {
        for (int c = 0; c < T; c++) {
            int j = i * T + c;
            if (j + 1 < myTotal) {
                asm volatile("cp.async.wait_group 1;" ::: "memory");
            } else {
                asm volatile("cp.async.wait_group 0;" ::: "memory");
            }
            __syncthreads();

            prefetchChunk(j + 2);

            unsigned aB = sbase + (unsigned)(j % 3) * STG;
            unsigned bB = aB + 16384u;

            unsigned afrag[2][4][4], bfrag[2][4][4];
            #pragma unroll
            for (int mi = 0; mi < 4; mi++)
                ldsm4(afrag[0][mi], aB + swz(wm * 64 + mi * 16 + lrow16, lhalf));
            #pragma unroll
            for (int p = 0; p < 4; p++)
                ldsm4(bfrag[0][p], bB + swz(wn * 64 + p * 16 + lrow16, lhalf));

            #pragma unroll
            for (int ks = 0; ks < 4; ks++) {
                int cur = ks & 1, nxt = cur ^ 1;
                if (ks < 3) {
                    #pragma unroll
                    for (int mi = 0; mi < 4; mi++)
                        ldsm4(afrag[nxt][mi], aB + swz(wm * 64 + mi * 16 + lrow16, (ks + 1) * 2 + lhalf));
                    #pragma unroll
                    for (int p = 0; p < 4; p++)
                        ldsm4(bfrag[nxt][p], bB + swz(wn * 64 + p * 16 + lrow16, (ks + 1) * 2 + lhalf));
                }
                #pragma unroll
                for (int mi = 0; mi < 4; mi++) {
                    #pragma unroll
                    for (int ni = 0; ni < 8; ni++) {
                        const unsigned* bf = bfrag[cur][ni >> 1];
                        if (IN8) mma_e4m3(acc[mi][ni], afrag[cur][mi], bf[ni & 1], bf[2 + (ni & 1)]);
                        else     mma_bf16(acc[mi][ni], afrag[cur][mi], bf[ni & 1], bf[2 + (ni & 1)]);
                    }
                }
            }
        }

        // ---------------- epilogue (overlaps the already-issued next-tile prefetch) ----------------
        {
            int tid2 = (int)blockIdx.x + i * G;
            int z = tid2 / gxy; int rr = tid2 - z * gxy;
            int by = rr / gx, bx = rr - by * gx;
            int m0 = by * 128, n0 = bx * 256;
            const int g = lane >> 2, tig = lane & 3;
            #pragma unroll
            for (int mi = 0; mi < 4; mi++) {
                #pragma unroll
                for (int half = 0; half < 2; half++) {
                    int row = m0 + wm * 64 + mi * 16 + g + half * 8;
                    float rs = 0.0f;
                    if (EPI == 4) rs = 1.0f / dptr[z * sRS + row];
                    float rsum = 0.0f;
                    #pragma unroll
                    for (int ni = 0; ni < 8; ni++) {
                        int col = n0 + wn * 64 + ni * 8 + tig * 2;
                        float v0 = acc[mi][ni][half * 2];
                        float v1 = acc[mi][ni][half * 2 + 1];
                        if (EPI == 1) { v0 += bias[col]; v1 += bias[col + 1]; }
                        if (EPI == 2) { v0 = exp2f(v0 * alpha); v1 = exp2f(v1 * alpha); rsum += v0 + v1; }
                        if (EPI == 4) {
                            const float* rp = resid + z * sR + (long long)row * ldc + col;
                            v0 = v0 * rs + bias[col] + rp[0];
                            v1 = v1 * rs + bias[col + 1] + rp[1];
                            float* C = (float*)Cv + z * sC;
                            *(float2*)(C + (long long)row * ldc + col) = make_float2(v0, v1);
                        } else {
                            __nv_bfloat16* C = (__nv_bfloat16*)Cv + z * sC;
                            __nv_bfloat162 pv = {__float2bfloat16(v0), __float2bfloat16(v1)};
                            *(__nv_bfloat162*)(C + (long long)row * ldc + col) = pv;
                        }
                    }
                    if (EPI == 2) {
                        rsum += __shfl_xor_sync(0xffffffffu, rsum, 1);
                        rsum += __shfl_xor_sync(0xffffffffu, rsum, 2);
                        if (tig == 0) atomicAdd(dptr + z * sRS + row, rsum);
                    }
                }
            }
        }
        #pragma unroll
        for (int a = 0; a < 4; a++)
            #pragma unroll
            for (int b = 0; b < 8; b++)
                #pragma unroll
                for (int v = 0; v < 4; v++) acc[a][b][v] = 0.0f;
    }
}

// ---------------- launch ----------------
extern "C" void kernel_launch(void* const* d_in, const int* in_sizes, int n_in,
                              void* d_out, int out_size) {
    const float* x      = (const float*)d_in[0];
    const float* g_norm = (const float*)d_in[1];
    const float* w_qkv  = (const float*)d_in[2];
    const float* b_qkv  = (const float*)d_in[3];
    const float* w_proj = (const float*)d_in[4];
    const float* b_proj = (const float*)d_in[5];
    float* out = (float*)d_out;

    void *pqkv, *pP, *ph, *pq, *pk, *pvw, *pwq, *pwp, *pd;
    cudaGetSymbolAddress(&pqkv, g_qkvbf);
    cudaGetSymbolAddress(&pP, g_P);
    cudaGetSymbolAddress(&ph, g_hbf);
    cudaGetSymbolAddress(&pq, g_qf8);
    cudaGetSymbolAddress(&pk, g_kf8);
    cudaGetSymbolAddress(&pvw, g_vwT);
    cudaGetSymbolAddress(&pwq, g_wqkvT);
    cudaGetSymbolAddress(&pwp, g_wprojT);
    cudaGetSymbolAddress(&pd, g_den);
    __nv_bfloat16* qkvbf = (__nv_bfloat16*)pqkv;
    __nv_bfloat16* P     = (__nv_bfloat16*)pP;
    __nv_bfloat16* hbf   = (__nv_bfloat16*)ph;
    unsigned char* qf8   = (unsigned char*)pq;
    unsigned char* kf8   = (unsigned char*)pk;
    __nv_bfloat16* vwT   = (__nv_bfloat16*)pvw;
    __nv_bfloat16* wqkvT = (__nv_bfloat16*)pwq;
    __nv_bfloat16* wprojT= (__nv_bfloat16*)pwp;
    float* den           = (float*)pd;

    int sm = 148;
    cudaDeviceGetAttribute(&sm, cudaDevAttrMultiProcessorCount, 0);

    const int SMEM = 3 * (int)STG;   // 144KB
    cudaFuncSetAttribute(gemm_tc<0,1>, cudaFuncAttributeMaxDynamicSharedMemorySize, SMEM);
    cudaFuncSetAttribute(gemm_tc<1,2>, cudaFuncAttributeMaxDynamicSharedMemorySize, SMEM);
    cudaFuncSetAttribute(gemm_tc<0,3>, cudaFuncAttributeMaxDynamicSharedMemorySize, SMEM);
    cudaFuncSetAttribute(gemm_tc<0,4>, cudaFuncAttributeMaxDynamicSharedMemorySize, SMEM);

    // 1) tables + weight transposes + rmsnorm + den zero
    build_inv_kernel<<<1, HALF>>>();
    build_tables_kernel<<<(SS * HALF + 255) / 256, 256>>>();
    transpose_cvt_kernel<<<dim3(TD / 32, DD / 32), 256>>>(w_qkv, TD, wqkvT, DD);
    transpose_cvt_kernel<<<dim3(DD / 32, DD / 32), 256>>>(w_proj, DD, wprojT, DD);
    rmsnorm_kernel<<<BB * SS, 256>>>(x, g_norm, hbf);
    zero_den_kernel<<<BB * SS / 256, 256>>>(den);

    // 2) qkv = h @ w_qkv + b_qkv  -> bf16   (M=16384,N=3072,K=1024)
    {
        int gx = TD / 256, gy = (BB * SS) / 128, gz = 1;
        int nt = gx * gy * gz, G = nt < sm ? nt : sm;
        gemm_tc<0,1><<<G, 256, SMEM>>>(
            DD * 2 / 128, gx, gy, gz,
            (const char*)hbf, DD * 2, 0LL,
            (const char*)wqkvT, DD * 2, 0LL,
            qkvbf, TD, 0LL,
            1.0f, b_qkv, nullptr, 0LL, nullptr, 0LL);
    }

    // 3) rope -> q,k fp8 ; vwT = wprojT @ V^T  (M=1024,N=4096,K=1024 per batch) — replaces V transpose + final-proj GEMM
    rope_kernel<<<BB * SS, 256>>>(qkvbf, (unsigned short*)qf8, (unsigned short*)kf8);
    {
        int gx = SS / 256, gy = DD / 128, gz = BB;
        int nt = gx * gy * gz, G = nt < sm ? nt : sm;
        gemm_tc<0,3><<<G, 256, SMEM>>>(
            DD * 2 / 128, gx, gy, gz,
            (const char*)wprojT, DD * 2, 0LL,
            (const char*)(qkvbf + 2 * DD), (long long)TD * 2, (long long)SS * TD * 2,
            vwT, SS, (long long)DD * SS,
            1.0f, nullptr, nullptr, 0LL, nullptr, 0LL);
    }

    // 4) P = 3^(q@k^T / 32) -> bf16, fused row-sum atomics into den  (M=N=4096,K=1024 fp8)
    {
        int gx = SS / 256, gy = SS / 128, gz = BB;
        int nt = gx * gy * gz, G = nt < sm ? nt : sm;
        gemm_tc<1,2><<<G, 256, SMEM>>>(
            DD / 128, gx, gy, gz,
            (const char*)qf8, DD, (long long)SS * DD,
            (const char*)kf8, DD, (long long)SS * DD,
            P, SS, (long long)SS * SS,
            1.5849625007211562f / 32.0f, nullptr, nullptr, 0LL, den, (long long)SS);
    }

    // 5) out = (P @ vwT^T)/den + b_proj + x  -> f32   (M=4096,N=1024,K=4096 per batch)
    {
        int gx = DD / 256, gy = SS / 128, gz = BB;
        int nt = gx * gy * gz, G = nt < sm ? nt : sm;
        gemm_tc<0,4><<<G, 256, SMEM>>>(
            SS * 2 / 128, gx, gy, gz,
            (const char*)P, (long long)SS * 2, (long long)SS * SS * 2,
            (const char*)vwT, (long long)SS * 2, (long long)DD * SS * 2,
            out, DD, (long long)SS * DD,
            1.0f, b_proj, x, (long long)SS * DD, den, (long long)SS);
    }
}